// round 1
// baseline (speedup 1.0000x reference)
#include <cuda_runtime.h>

// Problem dims (fixed by the reference)
#define BB   256      // batch
#define TT   512      // timesteps
#define EE   512      // input dim
#define HH   1024     // hidden dim
#define LDR  ((long)TT * HH)   // row stride between batches in d_out

// ---------------------------------------------------------------------------
// Phase 1: xh = x @ Wxh + bxh       (M=131072, N=1024, K=512) -> d_out
// Classic 128x128x8 SGEMM, 256 threads, 8x8 per thread.
// ---------------------------------------------------------------------------
__global__ void __launch_bounds__(256)
gemm_xh(const float* __restrict__ A,     // [M, 512] row-major
        const float* __restrict__ Bm,    // [512, 1024] row-major
        const float* __restrict__ bias,  // [1024]
        float* __restrict__ C)           // [M, 1024]
{
    const int N = HH, K = EE;
    const int BM = 128, BN = 128, BK = 8;
    __shared__ float As[BK][BM];
    __shared__ float Bs[BK][BN];

    const int bm = blockIdx.y, bn = blockIdx.x;
    const int tid = threadIdx.x;
    const int tx = tid & 15;      // 0..15
    const int ty = tid >> 4;      // 0..15

    float acc[8][8];
    #pragma unroll
    for (int i = 0; i < 8; i++)
        #pragma unroll
        for (int j = 0; j < 8; j++) acc[i][j] = 0.f;

    const float* Ab = A + (long)bm * BM * K;
    const float* Bb = Bm + bn * BN;

    const int arow = tid >> 1;            // 0..127
    const int acol = (tid & 1) * 4;       // 0 or 4
    const int brow = tid >> 5;            // 0..7
    const int bcol = (tid & 31) * 4;      // 0..124

    for (int k0 = 0; k0 < K; k0 += BK) {
        float4 av = *(const float4*)(Ab + (long)arow * K + k0 + acol);
        As[acol + 0][arow] = av.x;
        As[acol + 1][arow] = av.y;
        As[acol + 2][arow] = av.z;
        As[acol + 3][arow] = av.w;
        *(float4*)&Bs[brow][bcol] =
            *(const float4*)(Bb + (long)(k0 + brow) * N + bcol);
        __syncthreads();

        #pragma unroll
        for (int k = 0; k < BK; k++) {
            float4 a0 = *(const float4*)&As[k][ty * 8];
            float4 a1 = *(const float4*)&As[k][ty * 8 + 4];
            float4 b0 = *(const float4*)&Bs[k][tx * 8];
            float4 b1 = *(const float4*)&Bs[k][tx * 8 + 4];
            float ra[8] = {a0.x, a0.y, a0.z, a0.w, a1.x, a1.y, a1.z, a1.w};
            float rb[8] = {b0.x, b0.y, b0.z, b0.w, b1.x, b1.y, b1.z, b1.w};
            #pragma unroll
            for (int i = 0; i < 8; i++)
                #pragma unroll
                for (int j = 0; j < 8; j++)
                    acc[i][j] += ra[i] * rb[j];
        }
        __syncthreads();
    }

    #pragma unroll
    for (int i = 0; i < 8; i++) {
        long row = (long)bm * BM + ty * 8 + i;
        #pragma unroll
        for (int j = 0; j < 8; j += 4) {
            int col = bn * BN + tx * 8 + j;
            float4 o;
            o.x = acc[i][j + 0] + bias[col + 0];
            o.y = acc[i][j + 1] + bias[col + 1];
            o.z = acc[i][j + 2] + bias[col + 2];
            o.w = acc[i][j + 3] + bias[col + 3];
            *(float4*)(C + row * N + col) = o;
        }
    }
}

// ---------------------------------------------------------------------------
// t = 0:  h_0 = relu(xh_0)   (in place on slice 0)
// ---------------------------------------------------------------------------
__global__ void __launch_bounds__(256)
relu0(float* __restrict__ out)
{
    long idx = (long)blockIdx.x * 256 + threadIdx.x;   // over 256*1024
    int b = (int)(idx / HH);
    int h = (int)(idx % HH);
    float* p = out + (long)b * LDR + h;
    float v = *p;
    *p = v > 0.f ? v : 0.f;
}

// ---------------------------------------------------------------------------
// Phase 2 step t:  out[:,t,:] = relu(out[:,t,:] + out[:,t-1,:] @ Whh)
// M=256, N=1024, K=1024.  32x64x16 tiles, 128 threads, 4x4 per thread.
// 128 blocks -> ~1 block/SM.
// ---------------------------------------------------------------------------
__global__ void __launch_bounds__(128)
gemm_step(const float* __restrict__ Whh,   // [1024, 1024] row-major
          float* __restrict__ out,         // d_out base
          int t)
{
    const int N = HH, K = HH;
    const int BM = 32, BN = 64, BK = 16;
    __shared__ float As[BK][BM];
    __shared__ float Bs[BK][BN];

    const int bm = blockIdx.y, bn = blockIdx.x;
    const int tid = threadIdx.x;
    const int tx = tid & 15;     // 0..15
    const int ty = tid >> 4;     // 0..7

    float acc[4][4];
    #pragma unroll
    for (int i = 0; i < 4; i++)
        #pragma unroll
        for (int j = 0; j < 4; j++) acc[i][j] = 0.f;

    const float* Aprev = out + (long)(t - 1) * HH;   // + b*LDR per row
    float*       Cc    = out + (long)t * HH;

    const int arow = tid >> 2;          // 0..31
    const int acol = (tid & 3) * 4;     // 0..12

    for (int k0 = 0; k0 < K; k0 += BK) {
        float4 av = *(const float4*)(Aprev + (long)(bm * BM + arow) * LDR + k0 + acol);
        As[acol + 0][arow] = av.x;
        As[acol + 1][arow] = av.y;
        As[acol + 2][arow] = av.z;
        As[acol + 3][arow] = av.w;

        #pragma unroll
        for (int u = 0; u < 2; u++) {
            int fi = tid * 2 + u;          // float4 index 0..255
            int br = fi >> 4;              // 0..15
            int bc = (fi & 15) * 4;        // 0..60
            *(float4*)&Bs[br][bc] =
                *(const float4*)(Whh + (long)(k0 + br) * N + bn * BN + bc);
        }
        __syncthreads();

        #pragma unroll
        for (int k = 0; k < BK; k++) {
            float4 a = *(const float4*)&As[k][ty * 4];
            float4 b = *(const float4*)&Bs[k][tx * 4];
            float ra[4] = {a.x, a.y, a.z, a.w};
            float rb[4] = {b.x, b.y, b.z, b.w};
            #pragma unroll
            for (int i = 0; i < 4; i++)
                #pragma unroll
                for (int j = 0; j < 4; j++)
                    acc[i][j] += ra[i] * rb[j];
        }
        __syncthreads();
    }

    #pragma unroll
    for (int i = 0; i < 4; i++) {
        long row = bm * BM + ty * 4 + i;       // batch index
        int  col = bn * BN + tx * 4;
        float* p = Cc + row * LDR + col;
        float4 old = *(float4*)p;
        float4 o;
        o.x = fmaxf(old.x + acc[i][0], 0.f);
        o.y = fmaxf(old.y + acc[i][1], 0.f);
        o.z = fmaxf(old.z + acc[i][2], 0.f);
        o.w = fmaxf(old.w + acc[i][3], 0.f);
        *(float4*)p = o;
    }
}

// ---------------------------------------------------------------------------
extern "C" void kernel_launch(void* const* d_in, const int* in_sizes, int n_in,
                              void* d_out, int out_size)
{
    const float* x    = (const float*)d_in[0];   // [256,512,512]
    const float* Wxh  = (const float*)d_in[1];   // [512,1024]
    const float* bxh  = (const float*)d_in[2];   // [1024]
    const float* Whh  = (const float*)d_in[3];   // [1024,1024]
    float* out = (float*)d_out;                  // [256,512,1024]

    // Phase 1: xh -> d_out
    dim3 g1(HH / 128, (BB * TT) / 128);          // (8, 1024)
    gemm_xh<<<g1, 256>>>(x, Wxh, bxh, out);

    // t = 0
    relu0<<<(BB * HH) / 256, 256>>>(out);

    // Sequential scan t = 1..511
    dim3 g2(HH / 64, BB / 32);                   // (16, 8) = 128 blocks
    for (int t = 1; t < TT; t++)
        gemm_step<<<g2, 128>>>(Whh, out, t);
}

// round 3
// speedup vs baseline: 1.4352x; 1.4352x over previous
#include <cuda_runtime.h>

// Problem dims (fixed by the reference)
#define BB   256      // batch
#define TT   512      // timesteps
#define EE   512      // input dim
#define HH   1024     // hidden dim
#define LDR  ((long)TT * HH)   // row stride between batches in d_out

#define NBLK 128      // persistent blocks (one wave)
#define BM   64       // batch rows per block
#define BN   32       // hidden cols per block
#define BK   32       // k-chunk
#define APAD 68       // padded row stride for As (16B aligned)

// ---------------------------------------------------------------------------
// Grid-wide barrier state
// ---------------------------------------------------------------------------
__device__ unsigned int g_bar = 0;

__global__ void bar_reset() { g_bar = 0; }

__device__ __forceinline__ void grid_bar(unsigned target) {
    __syncthreads();
    if (threadIdx.x == 0) {
        __threadfence();                       // release all prior writes
        atomicAdd(&g_bar, 1u);
        volatile unsigned* p = &g_bar;
        while (*p < target) __nanosleep(64);
        __threadfence();                       // acquire
    }
    __syncthreads();
}

// ---------------------------------------------------------------------------
// Phase 1: xh = x @ Wxh + bxh       (M=131072, N=1024, K=512) -> d_out
// ---------------------------------------------------------------------------
__global__ void __launch_bounds__(256)
gemm_xh(const float* __restrict__ A,     // [M, 512] row-major
        const float* __restrict__ Bm,    // [512, 1024] row-major
        const float* __restrict__ bias,  // [1024]
        float* __restrict__ C)           // [M, 1024]
{
    const int N = HH, K = EE;
    const int TBM = 128, TBN = 128, TBK = 8;
    __shared__ float As[TBK][TBM];
    __shared__ float Bs[TBK][TBN];

    const int bm = blockIdx.y, bn = blockIdx.x;
    const int tid = threadIdx.x;
    const int tx = tid & 15;
    const int ty = tid >> 4;

    float acc[8][8];
    #pragma unroll
    for (int i = 0; i < 8; i++)
        #pragma unroll
        for (int j = 0; j < 8; j++) acc[i][j] = 0.f;

    const float* Ab = A + (long)bm * TBM * K;
    const float* Bb = Bm + bn * TBN;

    const int arow = tid >> 1;
    const int acol = (tid & 1) * 4;
    const int brow = tid >> 5;
    const int bcol = (tid & 31) * 4;

    for (int k0 = 0; k0 < K; k0 += TBK) {
        float4 av = *(const float4*)(Ab + (long)arow * K + k0 + acol);
        As[acol + 0][arow] = av.x;
        As[acol + 1][arow] = av.y;
        As[acol + 2][arow] = av.z;
        As[acol + 3][arow] = av.w;
        *(float4*)&Bs[brow][bcol] =
            *(const float4*)(Bb + (long)(k0 + brow) * N + bcol);
        __syncthreads();

        #pragma unroll
        for (int k = 0; k < TBK; k++) {
            float4 a0 = *(const float4*)&As[k][ty * 8];
            float4 a1 = *(const float4*)&As[k][ty * 8 + 4];
            float4 b0 = *(const float4*)&Bs[k][tx * 8];
            float4 b1 = *(const float4*)&Bs[k][tx * 8 + 4];
            float ra[8] = {a0.x, a0.y, a0.z, a0.w, a1.x, a1.y, a1.z, a1.w};
            float rb[8] = {b0.x, b0.y, b0.z, b0.w, b1.x, b1.y, b1.z, b1.w};
            #pragma unroll
            for (int i = 0; i < 8; i++)
                #pragma unroll
                for (int j = 0; j < 8; j++)
                    acc[i][j] += ra[i] * rb[j];
        }
        __syncthreads();
    }

    #pragma unroll
    for (int i = 0; i < 8; i++) {
        long row = (long)bm * TBM + ty * 8 + i;
        #pragma unroll
        for (int j = 0; j < 8; j += 4) {
            int col = bn * TBN + tx * 8 + j;
            float4 o;
            o.x = acc[i][j + 0] + bias[col + 0];
            o.y = acc[i][j + 1] + bias[col + 1];
            o.z = acc[i][j + 2] + bias[col + 2];
            o.w = acc[i][j + 3] + bias[col + 3];
            *(float4*)(C + row * N + col) = o;
        }
    }
}

// ---------------------------------------------------------------------------
// Phase 2: persistent scan kernel.
// 128 blocks; block b owns tile (bm = b>>5 row-tile of 4, bn = b&31 col-tile
// of 32). Whh[:, bn*32 .. +32) cached in smem ONCE (128 KB) and reused for
// all 511 steps. Per step: stream h_{t-1} through a double-buffered smem
// tile, FMA into a 4x2 register tile, fuse +xh and relu in place on slice t,
// then grid-wide barrier.
// ---------------------------------------------------------------------------
extern __shared__ float smem[];

__global__ void __launch_bounds__(256, 1)
rnn_scan(const float* __restrict__ Whh,   // [1024,1024] row-major
         float* __restrict__ out)         // d_out [256,512,1024], xh preloaded
{
    float* Wl  = smem;                    // [1024*32]  Wl[k*BN + n]
    float* As0 = smem + HH * BN;          // [BK*APAD]
    float* As1 = As0 + BK * APAD;

    const int tid = threadIdx.x;
    const int bn  = blockIdx.x & 31;
    const int bm  = blockIdx.x >> 5;
    const int tx  = tid & 15;             // col pair 0..15
    const int ty  = tid >> 4;             // row quad 0..15

    // ---- load Whh slice into smem: Wl[k*32 + n] ----
    {
        const float* src = Whh + bn * BN;
        #pragma unroll
        for (int i = 0; i < 32; i++) {
            int f  = tid + i * 256;        // float4 id 0..8191
            int k  = f >> 3;
            int n4 = (f & 7) * 4;
            *(float4*)&Wl[k * BN + n4] = *(const float4*)&src[(long)k * HH + n4];
        }
    }

    // ---- t = 0: h_0 = relu(xh_0) on own tile ----
    #pragma unroll
    for (int i = 0; i < 4; i++) {
        long base = (long)(bm * BM + ty * 4 + i) * LDR + bn * BN + tx * 2;
        float2 v = *(float2*)&out[base];
        v.x = fmaxf(v.x, 0.f);
        v.y = fmaxf(v.y, 0.f);
        *(float2*)&out[base] = v;
    }

    unsigned nbar = 1;
    grid_bar(nbar * NBLK);                 // h_0 visible everywhere

    // A-staging thread mapping: 8 consecutive floats per thread
    const int r  = tid >> 2;               // 0..63 (batch row in tile)
    const int kb = (tid & 3) * 8;          // 0,8,16,24 (k offset in chunk)
    const long rowA = (long)(bm * BM + r) * LDR;

    for (int t = 1; t < TT; t++) {
        const float* hp = out + (long)(t - 1) * HH;

        float acc[4][2];
        #pragma unroll
        for (int i = 0; i < 4; i++) { acc[i][0] = 0.f; acc[i][1] = 0.f; }

        // prefetch chunk 0 -> As0
        {
            const float* p = hp + rowA;
            float4 v0 = *(const float4*)&p[kb];
            float4 v1 = *(const float4*)&p[kb + 4];
            As0[(kb + 0) * APAD + r] = v0.x;
            As0[(kb + 1) * APAD + r] = v0.y;
            As0[(kb + 2) * APAD + r] = v0.z;
            As0[(kb + 3) * APAD + r] = v0.w;
            As0[(kb + 4) * APAD + r] = v1.x;
            As0[(kb + 5) * APAD + r] = v1.y;
            As0[(kb + 6) * APAD + r] = v1.z;
            As0[(kb + 7) * APAD + r] = v1.w;
        }
        __syncthreads();

        int buf = 0;
        for (int kc = 0; kc < HH / BK; kc++) {
            float4 n0, n1;
            const bool more = (kc + 1 < HH / BK);
            if (more) {
                const float* p = hp + rowA + (kc + 1) * BK;
                n0 = *(const float4*)&p[kb];
                n1 = *(const float4*)&p[kb + 4];
            }

            const float* A  = buf ? As1 : As0;
            const float* Wc = Wl + (kc * BK) * BN;   // <-- FIX: advance Whh rows
            #pragma unroll
            for (int k = 0; k < BK; k++) {
                float4 a = *(const float4*)&A[k * APAD + ty * 4];
                float2 b = *(const float2*)&Wc[k * BN + tx * 2];
                acc[0][0] += a.x * b.x; acc[0][1] += a.x * b.y;
                acc[1][0] += a.y * b.x; acc[1][1] += a.y * b.y;
                acc[2][0] += a.z * b.x; acc[2][1] += a.z * b.y;
                acc[3][0] += a.w * b.x; acc[3][1] += a.w * b.y;
            }

            if (more) {
                float* An = buf ? As0 : As1;
                An[(kb + 0) * APAD + r] = n0.x;
                An[(kb + 1) * APAD + r] = n0.y;
                An[(kb + 2) * APAD + r] = n0.z;
                An[(kb + 3) * APAD + r] = n0.w;
                An[(kb + 4) * APAD + r] = n1.x;
                An[(kb + 5) * APAD + r] = n1.y;
                An[(kb + 6) * APAD + r] = n1.z;
                An[(kb + 7) * APAD + r] = n1.w;
                __syncthreads();
                buf ^= 1;
            }
        }

        // epilogue: h_t = relu(xh_t + acc), in place on slice t
        float* ct = out + (long)t * HH;
        #pragma unroll
        for (int i = 0; i < 4; i++) {
            long base = (long)(bm * BM + ty * 4 + i) * LDR + bn * BN + tx * 2;
            float2 xv = *(float2*)&ct[base];
            xv.x = fmaxf(xv.x + acc[i][0], 0.f);
            xv.y = fmaxf(xv.y + acc[i][1], 0.f);
            *(float2*)&ct[base] = xv;
        }

        if (t < TT - 1) {
            nbar++;
            grid_bar(nbar * NBLK);
        }
    }
}

// ---------------------------------------------------------------------------
extern "C" void kernel_launch(void* const* d_in, const int* in_sizes, int n_in,
                              void* d_out, int out_size)
{
    const float* x    = (const float*)d_in[0];   // [256,512,512]
    const float* Wxh  = (const float*)d_in[1];   // [512,1024]
    const float* bxh  = (const float*)d_in[2];   // [1024]
    const float* Whh  = (const float*)d_in[3];   // [1024,1024]
    float* out = (float*)d_out;                  // [256,512,1024]

    // Phase 1: xh -> d_out
    dim3 g1(HH / 128, (BB * TT) / 128);          // (8, 1024)
    gemm_xh<<<g1, 256>>>(x, Wxh, bxh, out);

    // Phase 2: persistent scan (one wave of 128 blocks)
    const int smem_bytes = (HH * BN + 2 * BK * APAD) * (int)sizeof(float);
    cudaFuncSetAttribute(rnn_scan,
                         cudaFuncAttributeMaxDynamicSharedMemorySize,
                         smem_bytes);
    rnn_scan<<<NBLK, 256, smem_bytes>>>(Whh, out);

    // reset barrier counter for the next graph replay (stream-ordered)
    bar_reset<<<1, 1>>>();
}

// round 5
// speedup vs baseline: 2.4050x; 1.6758x over previous
#include <cuda_runtime.h>
#include <cuda_bf16.h>

// Problem dims (fixed by the reference)
#define BB   256      // batch
#define TT   512      // timesteps
#define EE   512      // input dim
#define HH   1024     // hidden dim
#define LDR  ((long)TT * HH)   // row stride between batches in d_out

#define NCTA 128      // persistent CTAs: 4 M-tiles (64 rows) x 32 N-tiles (32 cols)

// ---------------------------------------------------------------------------
// Scratch (device globals; no allocation allowed)
// g_A[buf][row][k]: packed bf16 hidden state: k<1024 = hi, k>=1024 = lo
// g_Wkn[kk][n]:     bf16 Whh in [k][n] layout: kk<1024 = hi, kk>=1024 = lo
// ---------------------------------------------------------------------------
__device__ __nv_bfloat16 g_A[2][BB][2048];
__device__ __nv_bfloat16 g_Wkn[2048][HH];

// ---------------------------------------------------------------------------
// PTX helpers (family-stable instructions only: ldmatrix + mma.sync)
// ---------------------------------------------------------------------------
__device__ __forceinline__ unsigned smem_u32(const void* p) {
    unsigned a;
    asm("{ .reg .u64 t; cvta.to.shared.u64 t, %1; cvt.u32.u64 %0, t; }"
        : "=r"(a) : "l"(p));
    return a;
}

#define LDSM4(r, a) \
    asm volatile("ldmatrix.sync.aligned.m8n8.x4.shared.b16 {%0,%1,%2,%3}, [%4];" \
        : "=r"((r)[0]), "=r"((r)[1]), "=r"((r)[2]), "=r"((r)[3]) : "r"(a))

#define LDSM4T(r, a) \
    asm volatile("ldmatrix.sync.aligned.m8n8.x4.trans.shared.b16 {%0,%1,%2,%3}, [%4];" \
        : "=r"((r)[0]), "=r"((r)[1]), "=r"((r)[2]), "=r"((r)[3]) : "r"(a))

__device__ __forceinline__ void mma16816(float* d, const unsigned* a,
                                         unsigned b0, unsigned b1) {
    asm volatile(
        "mma.sync.aligned.m16n8k16.row.col.f32.bf16.bf16.f32 "
        "{%0,%1,%2,%3}, {%4,%5,%6,%7}, {%8,%9}, {%0,%1,%2,%3};"
        : "+f"(d[0]), "+f"(d[1]), "+f"(d[2]), "+f"(d[3])
        : "r"(a[0]), "r"(a[1]), "r"(a[2]), "r"(a[3]), "r"(b0), "r"(b1));
}

// ---------------------------------------------------------------------------
// Grid-wide barrier
// ---------------------------------------------------------------------------
__device__ unsigned int g_bar = 0;
__global__ void bar_reset() { g_bar = 0; }

__device__ __forceinline__ void grid_bar(unsigned target) {
    __syncthreads();
    if (threadIdx.x == 0) {
        __threadfence();
        atomicAdd(&g_bar, 1u);
        volatile unsigned* p = &g_bar;
        while (*p < target) __nanosleep(64);
        __threadfence();
    }
    __syncthreads();
}

// ---------------------------------------------------------------------------
// Phase 1: xh = x @ Wxh + bxh   (M=131072, N=1024, K=512) -> d_out  [unchanged]
// ---------------------------------------------------------------------------
__global__ void __launch_bounds__(256)
gemm_xh(const float* __restrict__ A, const float* __restrict__ Bm,
        const float* __restrict__ bias, float* __restrict__ C)
{
    const int N = HH, K = EE;
    const int TBM = 128, TBN = 128, TBK = 8;
    __shared__ float As[TBK][TBM];
    __shared__ float Bs[TBK][TBN];

    const int bm = blockIdx.y, bn = blockIdx.x;
    const int tid = threadIdx.x;
    const int tx = tid & 15;
    const int ty = tid >> 4;

    float acc[8][8];
    #pragma unroll
    for (int i = 0; i < 8; i++)
        #pragma unroll
        for (int j = 0; j < 8; j++) acc[i][j] = 0.f;

    const float* Ab = A + (long)bm * TBM * K;
    const float* Bb = Bm + bn * TBN;

    const int arow = tid >> 1;
    const int acol = (tid & 1) * 4;
    const int brow = tid >> 5;
    const int bcol = (tid & 31) * 4;

    for (int k0 = 0; k0 < K; k0 += TBK) {
        float4 av = *(const float4*)(Ab + (long)arow * K + k0 + acol);
        As[acol + 0][arow] = av.x;
        As[acol + 1][arow] = av.y;
        As[acol + 2][arow] = av.z;
        As[acol + 3][arow] = av.w;
        *(float4*)&Bs[brow][bcol] =
            *(const float4*)(Bb + (long)(k0 + brow) * N + bcol);
        __syncthreads();

        #pragma unroll
        for (int k = 0; k < TBK; k++) {
            float4 a0 = *(const float4*)&As[k][ty * 8];
            float4 a1 = *(const float4*)&As[k][ty * 8 + 4];
            float4 b0 = *(const float4*)&Bs[k][tx * 8];
            float4 b1 = *(const float4*)&Bs[k][tx * 8 + 4];
            float ra[8] = {a0.x, a0.y, a0.z, a0.w, a1.x, a1.y, a1.z, a1.w};
            float rb[8] = {b0.x, b0.y, b0.z, b0.w, b1.x, b1.y, b1.z, b1.w};
            #pragma unroll
            for (int i = 0; i < 8; i++)
                #pragma unroll
                for (int j = 0; j < 8; j++)
                    acc[i][j] += ra[i] * rb[j];
        }
        __syncthreads();
    }

    #pragma unroll
    for (int i = 0; i < 8; i++) {
        long row = (long)bm * TBM + ty * 8 + i;
        #pragma unroll
        for (int j = 0; j < 8; j += 4) {
            int col = bn * TBN + tx * 8 + j;
            float4 o;
            o.x = acc[i][j + 0] + bias[col + 0];
            o.y = acc[i][j + 1] + bias[col + 1];
            o.z = acc[i][j + 2] + bias[col + 2];
            o.w = acc[i][j + 3] + bias[col + 3];
            *(float4*)(C + row * N + col) = o;
        }
    }
}

// ---------------------------------------------------------------------------
// Prep: Whh -> bf16 hi/lo in [k][n] layout
// ---------------------------------------------------------------------------
__global__ void __launch_bounds__(256)
wt_convert(const float* __restrict__ Whh)
{
    int idx = blockIdx.x * 256 + threadIdx.x;   // 0 .. 1M-1
    int k = idx >> 10, n = idx & 1023;
    float w = Whh[(long)k * HH + n];
    __nv_bfloat16 hi = __float2bfloat16(w);
    __nv_bfloat16 lo = __float2bfloat16(w - __bfloat162float(hi));
    g_Wkn[k][n] = hi;
    g_Wkn[1024 + k][n] = lo;
}

// Prep: h_0 = relu(xh_0) in place + bf16 hi/lo into g_A[0]
__global__ void __launch_bounds__(256)
init_h0(float* __restrict__ out)
{
    int idx = blockIdx.x * 256 + threadIdx.x;   // 0 .. 256K-1
    int b = idx >> 10, c = idx & 1023;
    float v = out[(long)b * LDR + c];
    v = fmaxf(v, 0.f);
    out[(long)b * LDR + c] = v;
    __nv_bfloat16 hi = __float2bfloat16(v);
    __nv_bfloat16 lo = __float2bfloat16(v - __bfloat162float(hi));
    g_A[0][b][c] = hi;
    g_A[0][b][1024 + c] = lo;
}

// ---------------------------------------------------------------------------
// Phase 2: persistent mma.sync scan.
// CTA (bm = bid>>5: 64-row tile, bn = bid&31: 32-col tile), 128 threads =
// 4 warps, warp tile 32(r) x 16(c). W slice resident in SMEM (once):
// hi at +65536, lo at +131072; 4 panels of [1024k][8n], k-contiguous 16B rows
// (conflict-free ldmatrix.trans). A chunks (64r x 128k, hi+lo = 32KB) double-
// buffered at +0 with XOR-swizzled 16B slots (conflict-free STS.128 + LDSM).
// 3 products per k16: Ahi*Whi, Alo*Whi, Ahi*Wlo -> fp32 accum (12 mma).
// Epilogue: +xh, relu, write fp32 out + next-step bf16 hi/lo, grid barrier.
// ---------------------------------------------------------------------------
extern __shared__ char smx[];

// swizzled offset inside a 16KB A region: kg in 0..15 (8-col k-groups), r in 0..63
#define AF(kg, r) ((unsigned)((kg) * 1024 + ((r) >> 3) * 128 + ((((r) & 7) ^ ((kg) & 7)) * 16)))

__global__ void __launch_bounds__(128, 1)
rnn_scan_mma(float* __restrict__ out)
{
    const int tid  = threadIdx.x;
    const int wid  = tid >> 5;
    const int lane = tid & 31;
    const int wr   = wid >> 1;          // warp row 0..1 (32 rows each)
    const int wc   = wid & 1;           // warp col 0..1 (16 cols each)
    const int bm   = blockIdx.x >> 5;   // 0..3
    const int bn   = blockIdx.x & 31;   // 0..31

    const unsigned sb = smem_u32(smx);

    // ---- stage W slice into SMEM panels (once) ----
    // hi: [65536, +64KB), lo: [131072, +64KB); panel p: [1024][8] bf16, 16B rows
    for (int i = 0; i < 64; i++) {
        int kk = i * 32 + (tid >> 2);      // 0..2047
        int p  = tid & 3;
        uint4 v = *(const uint4*)&g_Wkn[kk][bn * 32 + p * 8];
        unsigned off = 65536u + (unsigned)(kk >> 10) * 65536u
                     + (unsigned)p * 16384u + (unsigned)(kk & 1023) * 16u;
        *(uint4*)(smx + off) = v;
    }
    __syncthreads();

    // per-thread ldmatrix lane addressing
    const int q   = lane >> 3;          // 0..3
    const int l7  = lane & 7;
    const int kgq = q >> 1;             // 0 or 1 (k 8-group within k16)
    // A: rows r(m) = wr*32 + m*16 + (q&1)*8 + l7 ; line = (r>>3)*128, slot = l7
    const unsigned lineA0 = (unsigned)(wr * 4 + (q & 1)) * 128u;         // m=0
    const unsigned lineA1 = (unsigned)(wr * 4 + 2 + (q & 1)) * 128u;     // m=1
    // W: panel = wc*2 + (q>>1), k = s16*16 + (q&1)*8 + l7
    const unsigned wbaseHi = sb + 65536u + (unsigned)(wc * 2 + kgq) * 16384u
                           + (unsigned)((q & 1) * 8 + l7) * 16u;
    const unsigned wbaseLo = wbaseHi + 65536u;

    // A staging mapping (LDG/STS)
    const int rs  = tid >> 3;           // 0..15 (+16 per pass)
    const int kg1 = tid & 7;            // k-group (and kg1+8 for second half)

    // epilogue mapping
    const int eg = lane >> 2;           // 0..7
    const int ei = lane & 3;            // 0..3

    unsigned nbar = 0;

    for (int t = 1; t < TT; t++) {
        const __nv_bfloat16* Ar = &g_A[(t + 1) & 1][bm * 64][0];

        float d[2][2][4];
        #pragma unroll
        for (int m = 0; m < 2; m++)
            #pragma unroll
            for (int nt = 0; nt < 2; nt++)
                #pragma unroll
                for (int j = 0; j < 4; j++) d[m][nt][j] = 0.f;

        uint4 v[16];

        // prefetch + stage chunk 0
        #pragma unroll
        for (int i = 0; i < 4; i++) {
            int r = rs + i * 16;
            const __nv_bfloat16* p = Ar + (long)r * 2048 + kg1 * 8;
            v[i * 4 + 0] = *(const uint4*)(p);
            v[i * 4 + 1] = *(const uint4*)(p + 64);
            v[i * 4 + 2] = *(const uint4*)(p + 1024);
            v[i * 4 + 3] = *(const uint4*)(p + 1088);
        }
        #pragma unroll
        for (int i = 0; i < 4; i++) {
            int r = rs + i * 16;
            unsigned o1 = AF(kg1, r), o2 = AF(kg1 + 8, r);
            *(uint4*)(smx + o1)          = v[i * 4 + 0];
            *(uint4*)(smx + o2)          = v[i * 4 + 1];
            *(uint4*)(smx + 16384u + o1) = v[i * 4 + 2];
            *(uint4*)(smx + 16384u + o2) = v[i * 4 + 3];
        }
        __syncthreads();

        for (int c = 0; c < 8; c++) {
            const bool more = (c + 1 < 8);
            if (more) {
                #pragma unroll
                for (int i = 0; i < 4; i++) {
                    int r = rs + i * 16;
                    const __nv_bfloat16* p = Ar + (long)r * 2048 + (c + 1) * 128 + kg1 * 8;
                    v[i * 4 + 0] = *(const uint4*)(p);
                    v[i * 4 + 1] = *(const uint4*)(p + 64);
                    v[i * 4 + 2] = *(const uint4*)(p + 1024);
                    v[i * 4 + 3] = *(const uint4*)(p + 1088);
                }
            }

            const unsigned B0 = sb + (unsigned)(c & 1) * 32768u;
            #pragma unroll
            for (int s = 0; s < 8; s++) {
                const int kg = 2 * s + kgq;
                const unsigned aoff = (unsigned)kg * 1024u
                                    + (unsigned)((l7 ^ (kg & 7)) * 16);
                unsigned ahi0[4], ahi1[4], alo0[4], alo1[4], wh[4], wl[4];
                LDSM4(ahi0, B0 + lineA0 + aoff);
                LDSM4(ahi1, B0 + lineA1 + aoff);
                LDSM4(alo0, B0 + 16384u + lineA0 + aoff);
                LDSM4(alo1, B0 + 16384u + lineA1 + aoff);
                const unsigned wko = (unsigned)(c * 8 + s) * 256u;
                LDSM4T(wh, wbaseHi + wko);
                LDSM4T(wl, wbaseLo + wko);

                mma16816(d[0][0], ahi0, wh[0], wh[1]);
                mma16816(d[0][1], ahi0, wh[2], wh[3]);
                mma16816(d[1][0], ahi1, wh[0], wh[1]);
                mma16816(d[1][1], ahi1, wh[2], wh[3]);
                mma16816(d[0][0], alo0, wh[0], wh[1]);
                mma16816(d[0][1], alo0, wh[2], wh[3]);
                mma16816(d[1][0], alo1, wh[0], wh[1]);
                mma16816(d[1][1], alo1, wh[2], wh[3]);
                mma16816(d[0][0], ahi0, wl[0], wl[1]);
                mma16816(d[0][1], ahi0, wl[2], wl[3]);
                mma16816(d[1][0], ahi1, wl[0], wl[1]);
                mma16816(d[1][1], ahi1, wl[2], wl[3]);
            }

            if (more) {
                const unsigned B1 = (unsigned)((c + 1) & 1) * 32768u;
                #pragma unroll
                for (int i = 0; i < 4; i++) {
                    int r = rs + i * 16;
                    unsigned o1 = B1 + AF(kg1, r), o2 = B1 + AF(kg1 + 8, r);
                    *(uint4*)(smx + o1)          = v[i * 4 + 0];
                    *(uint4*)(smx + o2)          = v[i * 4 + 1];
                    *(uint4*)(smx + 16384u + o1) = v[i * 4 + 2];
                    *(uint4*)(smx + 16384u + o2) = v[i * 4 + 3];
                }
                __syncthreads();
            }
        }

        // ---- epilogue: h_t = relu(xh_t + d), fp32 out + bf16 hi/lo next state
        __nv_bfloat16* An = &g_A[t & 1][0][0];
        #pragma unroll
        for (int m = 0; m < 2; m++) {
            #pragma unroll
            for (int half = 0; half < 2; half++) {
                const int r  = wr * 32 + m * 16 + eg + half * 8;
                const int gb = bm * 64 + r;
                #pragma unroll
                for (int nt = 0; nt < 2; nt++) {
                    const int ccol = bn * 32 + wc * 16 + nt * 8 + 2 * ei;
                    float* po = out + (long)gb * LDR + (long)t * HH + ccol;
                    float2 xv = *(float2*)po;
                    float s0 = fmaxf(xv.x + d[m][nt][half * 2 + 0], 0.f);
                    float s1 = fmaxf(xv.y + d[m][nt][half * 2 + 1], 0.f);
                    float2 ov = {s0, s1};
                    *(float2*)po = ov;

                    __nv_bfloat16 h0 = __float2bfloat16(s0);
                    __nv_bfloat16 h1 = __float2bfloat16(s1);
                    __nv_bfloat16 l0 = __float2bfloat16(s0 - __bfloat162float(h0));
                    __nv_bfloat16 l1 = __float2bfloat16(s1 - __bfloat162float(h1));
                    unsigned hp = (unsigned)__bfloat16_as_ushort(h0)
                                | ((unsigned)__bfloat16_as_ushort(h1) << 16);
                    unsigned lp = (unsigned)__bfloat16_as_ushort(l0)
                                | ((unsigned)__bfloat16_as_ushort(l1) << 16);
                    *(unsigned*)(An + (long)gb * 2048 + ccol)        = hp;
                    *(unsigned*)(An + (long)gb * 2048 + 1024 + ccol) = lp;
                }
            }
        }

        if (t < TT - 1) {
            nbar++;
            grid_bar(nbar * NCTA);
        }
    }
}

// ---------------------------------------------------------------------------
extern "C" void kernel_launch(void* const* d_in, const int* in_sizes, int n_in,
                              void* d_out, int out_size)
{
    const float* x   = (const float*)d_in[0];   // [256,512,512]
    const float* Wxh = (const float*)d_in[1];   // [512,1024]
    const float* bxh = (const float*)d_in[2];   // [1024]
    const float* Whh = (const float*)d_in[3];   // [1024,1024]
    float* out = (float*)d_out;                 // [256,512,1024]

    // Phase 1: xh -> d_out
    dim3 g1(HH / 128, (BB * TT) / 128);
    gemm_xh<<<g1, 256>>>(x, Wxh, bxh, out);

    // Prep: Whh -> bf16 hi/lo [k][n]; h0 = relu(xh_0) + bf16 split
    wt_convert<<<(HH * HH) / 256, 256>>>(Whh);
    init_h0<<<(BB * HH) / 256, 256>>>(out);

    // Phase 2: persistent mma.sync scan
    const int smem_bytes = 65536 + 2 * 65536;   // A 64KB + Whi 64KB + Wlo 64KB
    cudaFuncSetAttribute(rnn_scan_mma,
                         cudaFuncAttributeMaxDynamicSharedMemorySize,
                         smem_bytes);
    rnn_scan_mma<<<NCTA, 128, smem_bytes>>>(out);

    // reset grid barrier for next replay
    bar_reset<<<1, 1>>>();
}

// round 6
// speedup vs baseline: 3.0927x; 1.2860x over previous
#include <cuda_runtime.h>
#include <cuda_bf16.h>

// Problem dims (fixed by the reference)
#define BB   256      // batch
#define TT   512      // timesteps
#define EE   512      // input dim
#define HH   1024     // hidden dim
#define LDR  ((long)TT * HH)   // row stride between batches in d_out

#define NCTA 128      // persistent CTAs: 4 M-tiles (64 rows) x 32 N-tiles (32 cols)

// ---------------------------------------------------------------------------
// Scratch (device globals; no allocation allowed)
// g_A[buf][row][k]: packed bf16 hidden state: k<1024 = hi, k>=1024 = lo
// g_Wkn[kk][n]:     bf16 Whh in [k][n] layout: kk<1024 = hi, kk>=1024 = lo
// g_Wx[kk][n]:      bf16 Wxh in [k][n] layout: kk<512  = hi, kk>=512  = lo
// ---------------------------------------------------------------------------
__device__ __nv_bfloat16 g_A[2][BB][2048];
__device__ __nv_bfloat16 g_Wkn[2048][HH];
__device__ __nv_bfloat16 g_Wx[1024][HH];

// ---------------------------------------------------------------------------
// PTX helpers (family-stable instructions only: ldmatrix + mma.sync)
// ---------------------------------------------------------------------------
__device__ __forceinline__ unsigned smem_u32(const void* p) {
    unsigned a;
    asm("{ .reg .u64 t; cvta.to.shared.u64 t, %1; cvt.u32.u64 %0, t; }"
        : "=r"(a) : "l"(p));
    return a;
}

#define LDSM4(r, a) \
    asm volatile("ldmatrix.sync.aligned.m8n8.x4.shared.b16 {%0,%1,%2,%3}, [%4];" \
        : "=r"((r)[0]), "=r"((r)[1]), "=r"((r)[2]), "=r"((r)[3]) : "r"(a))

#define LDSM4T(r, a) \
    asm volatile("ldmatrix.sync.aligned.m8n8.x4.trans.shared.b16 {%0,%1,%2,%3}, [%4];" \
        : "=r"((r)[0]), "=r"((r)[1]), "=r"((r)[2]), "=r"((r)[3]) : "r"(a))

__device__ __forceinline__ void mma16816(float* d, const unsigned* a,
                                         unsigned b0, unsigned b1) {
    asm volatile(
        "mma.sync.aligned.m16n8k16.row.col.f32.bf16.bf16.f32 "
        "{%0,%1,%2,%3}, {%4,%5,%6,%7}, {%8,%9}, {%0,%1,%2,%3};"
        : "+f"(d[0]), "+f"(d[1]), "+f"(d[2]), "+f"(d[3])
        : "r"(a[0]), "r"(a[1]), "r"(a[2]), "r"(a[3]), "r"(b0), "r"(b1));
}

// pack 8 fp32 -> uint4 hi bf16, uint4 lo bf16
__device__ __forceinline__ void split8(float4 a, float4 b, uint4& hi, uint4& lo) {
    float s[8] = {a.x, a.y, a.z, a.w, b.x, b.y, b.z, b.w};
    unsigned h[4], l[4];
    #pragma unroll
    for (int i = 0; i < 4; i++) {
        __nv_bfloat16 h0 = __float2bfloat16(s[2 * i]);
        __nv_bfloat16 h1 = __float2bfloat16(s[2 * i + 1]);
        __nv_bfloat16 l0 = __float2bfloat16(s[2 * i] - __bfloat162float(h0));
        __nv_bfloat16 l1 = __float2bfloat16(s[2 * i + 1] - __bfloat162float(h1));
        h[i] = (unsigned)__bfloat16_as_ushort(h0)
             | ((unsigned)__bfloat16_as_ushort(h1) << 16);
        l[i] = (unsigned)__bfloat16_as_ushort(l0)
             | ((unsigned)__bfloat16_as_ushort(l1) << 16);
    }
    hi = make_uint4(h[0], h[1], h[2], h[3]);
    lo = make_uint4(l[0], l[1], l[2], l[3]);
}

// ---------------------------------------------------------------------------
// Grid-wide barrier
// ---------------------------------------------------------------------------
__device__ unsigned int g_bar = 0;
__global__ void bar_reset() { g_bar = 0; }

__device__ __forceinline__ void grid_bar(unsigned target) {
    __syncthreads();
    if (threadIdx.x == 0) {
        __threadfence();
        atomicAdd(&g_bar, 1u);
        volatile unsigned* p = &g_bar;
        while (*p < target) __nanosleep(64);
        __threadfence();
    }
    __syncthreads();
}

// ---------------------------------------------------------------------------
// Prep: weight conversions
// ---------------------------------------------------------------------------
__global__ void __launch_bounds__(256)
wt_convert(const float* __restrict__ Whh)
{
    int idx = blockIdx.x * 256 + threadIdx.x;   // 0 .. 1M-1
    int k = idx >> 10, n = idx & 1023;
    float w = Whh[(long)k * HH + n];
    __nv_bfloat16 hi = __float2bfloat16(w);
    __nv_bfloat16 lo = __float2bfloat16(w - __bfloat162float(hi));
    g_Wkn[k][n] = hi;
    g_Wkn[1024 + k][n] = lo;
}

__global__ void __launch_bounds__(256)
wx_convert(const float* __restrict__ Wxh)
{
    int idx = blockIdx.x * 256 + threadIdx.x;   // 0 .. 512K-1
    int k = idx >> 10, n = idx & 1023;
    float w = Wxh[(long)k * HH + n];
    __nv_bfloat16 hi = __float2bfloat16(w);
    __nv_bfloat16 lo = __float2bfloat16(w - __bfloat162float(hi));
    g_Wx[k][n] = hi;
    g_Wx[512 + k][n] = lo;
}

// Prep: h_0 = relu(xh_0) in place + bf16 hi/lo into g_A[0]
__global__ void __launch_bounds__(256)
init_h0(float* __restrict__ out)
{
    int idx = blockIdx.x * 256 + threadIdx.x;   // 0 .. 256K-1
    int b = idx >> 10, c = idx & 1023;
    float v = out[(long)b * LDR + c];
    v = fmaxf(v, 0.f);
    out[(long)b * LDR + c] = v;
    __nv_bfloat16 hi = __float2bfloat16(v);
    __nv_bfloat16 lo = __float2bfloat16(v - __bfloat162float(hi));
    g_A[0][b][c] = hi;
    g_A[0][b][1024 + c] = lo;
}

// ---------------------------------------------------------------------------
// Phase 1 (tensor): xh = x @ Wxh + bxh  via bf16 hi/lo 3-product mma.sync.
// CTA tile 128(m) x 128(n), K=512 chunked by 32 (double-buffered smem).
// 8 warps, warp tile 32(m) x 64(n). x converted fp32->hi/lo during staging.
// smem per buffer (32KB): [0,8K) Ahi  [8K,16K) Alo  [16K,24K) Whi  [24K,32K) Wlo
// ---------------------------------------------------------------------------
extern __shared__ char smx[];

// A-region offset: kg in 0..3 (8-k groups), m in 0..127
#define AFX(kg, m) ((unsigned)((kg) * 2048 + ((m) >> 3) * 128 + ((((m) & 7) ^ (kg)) * 16)))

__global__ void __launch_bounds__(256)
gemm_xh_mma(const float* __restrict__ x,     // [131072, 512]
            const float* __restrict__ bias,  // [1024]
            float* __restrict__ C)           // [131072, 1024]
{
    const int tid  = threadIdx.x;
    const int wid  = tid >> 5;
    const int lane = tid & 31;
    const int wr   = wid & 3;           // m: wr*32
    const int wc   = wid >> 2;          // n: wc*64
    const int bm   = blockIdx.y;
    const int bn   = blockIdx.x;

    const unsigned sb = smem_u32(smx);
    const int q   = lane >> 3;
    const int l7  = lane & 7;
    const int kgq = q >> 1;

    // staging thread mapping
    const int am = tid & 127;           // A: m row   (kg = (idx>>7))
    const int wk = tid & 31;            // W: k row   (p  = (idx>>5)&15)

    // bias regs: col = bn*128 + wc*64 + n8*8 + (lane&3)*2
    float2 breg[8];
    #pragma unroll
    for (int n8 = 0; n8 < 8; n8++)
        breg[n8] = *(const float2*)&bias[bn * 128 + wc * 64 + n8 * 8 + (lane & 3) * 2];

    float acc[2][8][4];
    #pragma unroll
    for (int m = 0; m < 2; m++)
        #pragma unroll
        for (int n = 0; n < 8; n++)
            #pragma unroll
            for (int j = 0; j < 4; j++) acc[m][n][j] = 0.f;

    const float* xb = x + (long)(bm * 128) * EE;

    // ---- prologue: load + stage chunk 0 into buf 0 ----
    float4 xa[2][2];
    uint4  wvh[2], wvl[2];
    #pragma unroll
    for (int i = 0; i < 2; i++) {
        int idx = tid + i * 256;
        int kg = idx >> 7;
        const float* p = xb + (long)am * EE + kg * 8;
        xa[i][0] = *(const float4*)p;
        xa[i][1] = *(const float4*)(p + 4);
        int pp = (idx >> 5) & 15;
        wvh[i] = *(const uint4*)&g_Wx[wk][bn * 128 + pp * 8];
        wvl[i] = *(const uint4*)&g_Wx[512 + wk][bn * 128 + pp * 8];
    }
    #pragma unroll
    for (int i = 0; i < 2; i++) {
        int idx = tid + i * 256;
        int kg = idx >> 7;
        uint4 hi, lo;
        split8(xa[i][0], xa[i][1], hi, lo);
        unsigned ao = AFX(kg, am);
        *(uint4*)(smx + ao)         = hi;
        *(uint4*)(smx + 8192 + ao)  = lo;
        int pp = (idx >> 5) & 15;
        unsigned wo = 16384u + (unsigned)pp * 512u + (unsigned)wk * 16u;
        *(uint4*)(smx + wo)         = wvh[i];
        *(uint4*)(smx + 8192 + wo)  = wvl[i];
    }
    __syncthreads();

    unsigned buf = 0;
    for (int kc = 0; kc < 16; kc++) {
        const bool more = (kc + 1 < 16);
        if (more) {
            const int k0 = (kc + 1) * 32;
            #pragma unroll
            for (int i = 0; i < 2; i++) {
                int idx = tid + i * 256;
                int kg = idx >> 7;
                const float* p = xb + (long)am * EE + k0 + kg * 8;
                xa[i][0] = *(const float4*)p;
                xa[i][1] = *(const float4*)(p + 4);
                int pp = (idx >> 5) & 15;
                wvh[i] = *(const uint4*)&g_Wx[k0 + wk][bn * 128 + pp * 8];
                wvl[i] = *(const uint4*)&g_Wx[512 + k0 + wk][bn * 128 + pp * 8];
            }
        }

        const unsigned B0 = sb + buf * 32768u;
        #pragma unroll
        for (int s16 = 0; s16 < 2; s16++) {
            const int kg = s16 * 2 + kgq;
            const unsigned aoff = (unsigned)kg * 2048u + (unsigned)((l7 ^ kg) * 16);
            unsigned ahi[2][4], alo[2][4];
            LDSM4(ahi[0], B0 + aoff + (unsigned)(wr * 4 + 0 + (q & 1)) * 128u);
            LDSM4(ahi[1], B0 + aoff + (unsigned)(wr * 4 + 2 + (q & 1)) * 128u);
            LDSM4(alo[0], B0 + 8192u + aoff + (unsigned)(wr * 4 + 0 + (q & 1)) * 128u);
            LDSM4(alo[1], B0 + 8192u + aoff + (unsigned)(wr * 4 + 2 + (q & 1)) * 128u);

            const unsigned wrow = (unsigned)(s16 * 16 + (q & 1) * 8 + l7) * 16u;
            #pragma unroll
            for (int pp = 0; pp < 4; pp++) {
                unsigned wh[4], wl[4];
                unsigned wbase = B0 + 16384u
                               + (unsigned)(wc * 8 + pp * 2 + kgq) * 512u + wrow;
                LDSM4T(wh, wbase);
                LDSM4T(wl, wbase + 8192u);
                const int n0 = pp * 2, n1 = pp * 2 + 1;
                mma16816(acc[0][n0], ahi[0], wh[0], wh[1]);
                mma16816(acc[0][n1], ahi[0], wh[2], wh[3]);
                mma16816(acc[1][n0], ahi[1], wh[0], wh[1]);
                mma16816(acc[1][n1], ahi[1], wh[2], wh[3]);
                mma16816(acc[0][n0], alo[0], wh[0], wh[1]);
                mma16816(acc[0][n1], alo[0], wh[2], wh[3]);
                mma16816(acc[1][n0], alo[1], wh[0], wh[1]);
                mma16816(acc[1][n1], alo[1], wh[2], wh[3]);
                mma16816(acc[0][n0], ahi[0], wl[0], wl[1]);
                mma16816(acc[0][n1], ahi[0], wl[2], wl[3]);
                mma16816(acc[1][n0], ahi[1], wl[0], wl[1]);
                mma16816(acc[1][n1], ahi[1], wl[2], wl[3]);
            }
        }

        if (more) {
            const unsigned nb = (buf ^ 1u) * 32768u;
            #pragma unroll
            for (int i = 0; i < 2; i++) {
                int idx = tid + i * 256;
                int kg = idx >> 7;
                uint4 hi, lo;
                split8(xa[i][0], xa[i][1], hi, lo);
                unsigned ao = nb + AFX(kg, am);
                *(uint4*)(smx + ao)        = hi;
                *(uint4*)(smx + 8192 + ao) = lo;
                int pp = (idx >> 5) & 15;
                unsigned wo = nb + 16384u + (unsigned)pp * 512u + (unsigned)wk * 16u;
                *(uint4*)(smx + wo)        = wvh[i];
                *(uint4*)(smx + 8192 + wo) = wvl[i];
            }
            __syncthreads();
            buf ^= 1u;
        }
    }

    // ---- epilogue: C = acc + bias ----
    #pragma unroll
    for (int mm = 0; mm < 2; mm++) {
        #pragma unroll
        for (int half = 0; half < 2; half++) {
            long row = (long)bm * 128 + wr * 32 + mm * 16 + (lane >> 2) + half * 8;
            float* pr = C + row * HH + bn * 128 + wc * 64 + (lane & 3) * 2;
            #pragma unroll
            for (int n8 = 0; n8 < 8; n8++) {
                float2 o;
                o.x = acc[mm][n8][half * 2 + 0] + breg[n8].x;
                o.y = acc[mm][n8][half * 2 + 1] + breg[n8].y;
                *(float2*)(pr + n8 * 8) = o;
            }
        }
    }
}

// ---------------------------------------------------------------------------
// Phase 2: persistent mma.sync scan, 256 threads / 8 warps.
// CTA (bm = bid>>5: 64-row tile, bn = bid&31: 32-col tile); warp tile 16x16:
// wr = wid>>1 (m), wc = wid&1 (n). W resident in SMEM (hi @64KB, lo @128KB,
// 4 panels of [1024k][8n] 16B rows). A chunks (64r x 128 packed k = 32KB)
// double-buffered at 0 with XOR-swizzled 16B slots.
// ---------------------------------------------------------------------------
#define AF(kg, r) ((unsigned)((kg) * 1024 + ((r) >> 3) * 128 + ((((r) & 7) ^ ((kg) & 7)) * 16)))

__global__ void __launch_bounds__(256, 1)
rnn_scan_mma(float* __restrict__ out)
{
    const int tid  = threadIdx.x;
    const int wid  = tid >> 5;
    const int lane = tid & 31;
    const int wr   = wid >> 1;          // warp row 0..3 (16 rows each)
    const int wc   = wid & 1;           // warp col 0..1 (16 cols each)
    const int bm   = blockIdx.x >> 5;   // 0..3
    const int bn   = blockIdx.x & 31;   // 0..31

    const unsigned sb = smem_u32(smx);

    // ---- stage W slice into SMEM panels (once) ----
    for (int i = 0; i < 32; i++) {
        int kk = i * 64 + (tid >> 2);      // 0..2047
        int p  = tid & 3;
        uint4 v = *(const uint4*)&g_Wkn[kk][bn * 32 + p * 8];
        unsigned off = 65536u + (unsigned)(kk >> 10) * 65536u
                     + (unsigned)p * 16384u + (unsigned)(kk & 1023) * 16u;
        *(uint4*)(smx + off) = v;
    }
    __syncthreads();

    // ldmatrix lane addressing
    const int q   = lane >> 3;
    const int l7  = lane & 7;
    const int kgq = q >> 1;
    const unsigned lineA = (unsigned)(wr * 2 + (q & 1)) * 128u;
    const unsigned wbaseHi = sb + 65536u + (unsigned)(wc * 2 + kgq) * 16384u
                           + (unsigned)((q & 1) * 8 + l7) * 16u;
    const unsigned wbaseLo = wbaseHi + 65536u;

    // A staging: thread -> (row rs2 + i*16, k-group kg2); hi and lo 16B each
    const int rs2 = tid >> 4;           // 0..15
    const int kg2 = tid & 15;           // 0..15

    // epilogue mapping
    const int eg = lane >> 2;
    const int ei = lane & 3;

    unsigned nbar = 0;

    for (int t = 1; t < TT; t++) {
        const __nv_bfloat16* Ar = &g_A[(t + 1) & 1][bm * 64][0];

        float d[2][4];
        #pragma unroll
        for (int nt = 0; nt < 2; nt++)
            #pragma unroll
            for (int j = 0; j < 4; j++) d[nt][j] = 0.f;

        uint4 v[8];

        // prefetch + stage chunk 0
        #pragma unroll
        for (int i = 0; i < 4; i++) {
            int r = rs2 + i * 16;
            const __nv_bfloat16* p = Ar + (long)r * 2048 + kg2 * 8;
            v[i * 2 + 0] = *(const uint4*)(p);
            v[i * 2 + 1] = *(const uint4*)(p + 1024);
        }
        #pragma unroll
        for (int i = 0; i < 4; i++) {
            int r = rs2 + i * 16;
            unsigned o1 = AF(kg2, r);
            *(uint4*)(smx + o1)          = v[i * 2 + 0];
            *(uint4*)(smx + 16384u + o1) = v[i * 2 + 1];
        }
        __syncthreads();

        for (int c = 0; c < 8; c++) {
            const bool more = (c + 1 < 8);
            if (more) {
                #pragma unroll
                for (int i = 0; i < 4; i++) {
                    int r = rs2 + i * 16;
                    const __nv_bfloat16* p = Ar + (long)r * 2048 + (c + 1) * 128 + kg2 * 8;
                    v[i * 2 + 0] = *(const uint4*)(p);
                    v[i * 2 + 1] = *(const uint4*)(p + 1024);
                }
            }

            const unsigned B0 = sb + (unsigned)(c & 1) * 32768u;
            #pragma unroll
            for (int s = 0; s < 8; s++) {
                const int kg = 2 * s + kgq;
                const unsigned aoff = (unsigned)kg * 1024u
                                    + (unsigned)((l7 ^ (kg & 7)) * 16);
                unsigned ahi[4], alo[4], wh[4], wl[4];
                LDSM4(ahi, B0 + lineA + aoff);
                LDSM4(alo, B0 + 16384u + lineA + aoff);
                const unsigned wko = (unsigned)(c * 8 + s) * 256u;
                LDSM4T(wh, wbaseHi + wko);
                LDSM4T(wl, wbaseLo + wko);

                mma16816(d[0], ahi, wh[0], wh[1]);
                mma16816(d[1], ahi, wh[2], wh[3]);
                mma16816(d[0], alo, wh[0], wh[1]);
                mma16816(d[1], alo, wh[2], wh[3]);
                mma16816(d[0], ahi, wl[0], wl[1]);
                mma16816(d[1], ahi, wl[2], wl[3]);
            }

            if (more) {
                const unsigned B1 = (unsigned)((c + 1) & 1) * 32768u;
                #pragma unroll
                for (int i = 0; i < 4; i++) {
                    int r = rs2 + i * 16;
                    unsigned o1 = B1 + AF(kg2, r);
                    *(uint4*)(smx + o1)          = v[i * 2 + 0];
                    *(uint4*)(smx + 16384u + o1) = v[i * 2 + 1];
                }
                __syncthreads();
            }
        }

        // ---- epilogue: h_t = relu(xh_t + d), fp32 out + bf16 hi/lo next state
        __nv_bfloat16* An = &g_A[t & 1][0][0];
        #pragma unroll
        for (int half = 0; half < 2; half++) {
            const int gb = bm * 64 + wr * 16 + eg + half * 8;
            #pragma unroll
            for (int nt = 0; nt < 2; nt++) {
                const int ccol = bn * 32 + wc * 16 + nt * 8 + 2 * ei;
                float* po = out + (long)gb * LDR + (long)t * HH + ccol;
                float2 xv = *(float2*)po;
                float s0 = fmaxf(xv.x + d[nt][half * 2 + 0], 0.f);
                float s1 = fmaxf(xv.y + d[nt][half * 2 + 1], 0.f);
                float2 ov = {s0, s1};
                *(float2*)po = ov;

                __nv_bfloat16 h0 = __float2bfloat16(s0);
                __nv_bfloat16 h1 = __float2bfloat16(s1);
                __nv_bfloat16 l0 = __float2bfloat16(s0 - __bfloat162float(h0));
                __nv_bfloat16 l1 = __float2bfloat16(s1 - __bfloat162float(h1));
                unsigned hp = (unsigned)__bfloat16_as_ushort(h0)
                            | ((unsigned)__bfloat16_as_ushort(h1) << 16);
                unsigned lp = (unsigned)__bfloat16_as_ushort(l0)
                            | ((unsigned)__bfloat16_as_ushort(l1) << 16);
                *(unsigned*)(An + (long)gb * 2048 + ccol)        = hp;
                *(unsigned*)(An + (long)gb * 2048 + 1024 + ccol) = lp;
            }
        }

        if (t < TT - 1) {
            nbar++;
            grid_bar(nbar * NCTA);
        }
    }
}

// ---------------------------------------------------------------------------
extern "C" void kernel_launch(void* const* d_in, const int* in_sizes, int n_in,
                              void* d_out, int out_size)
{
    const float* x   = (const float*)d_in[0];   // [256,512,512]
    const float* Wxh = (const float*)d_in[1];   // [512,1024]
    const float* bxh = (const float*)d_in[2];   // [1024]
    const float* Whh = (const float*)d_in[3];   // [1024,1024]
    float* out = (float*)d_out;                 // [256,512,1024]

    // Prep: weight splits
    wx_convert<<<(EE * HH) / 256, 256>>>(Wxh);
    wt_convert<<<(HH * HH) / 256, 256>>>(Whh);

    // Phase 1: xh -> d_out (tensor cores, bf16 hi/lo x3)
    const int smem_p1 = 2 * 32768;
    cudaFuncSetAttribute(gemm_xh_mma,
                         cudaFuncAttributeMaxDynamicSharedMemorySize, smem_p1);
    dim3 g1(HH / 128, (BB * TT) / 128);          // (8, 1024)
    gemm_xh_mma<<<g1, 256, smem_p1>>>(x, bxh, out);

    // h0 = relu(xh_0) + bf16 split
    init_h0<<<(BB * HH) / 256, 256>>>(out);

    // Phase 2: persistent mma.sync scan
    const int smem_p2 = 65536 + 2 * 65536;       // A dbl 64KB + W 128KB
    cudaFuncSetAttribute(rnn_scan_mma,
                         cudaFuncAttributeMaxDynamicSharedMemorySize, smem_p2);
    rnn_scan_mma<<<NCTA, 256, smem_p2>>>(out);

    // reset grid barrier for next replay
    bar_reset<<<1, 1>>>();
}

// round 7
// speedup vs baseline: 3.4597x; 1.1187x over previous
#include <cuda_runtime.h>
#include <cuda_bf16.h>

// Problem dims (fixed by the reference)
#define BB   256      // batch
#define TT   512      // timesteps
#define EE   512      // input dim
#define HH   1024     // hidden dim
#define LDR  ((long)TT * HH)   // row stride between batches in d_out

#define NCTA 128      // persistent CTAs: 4 M-tiles (64 rows) x 32 N-tiles (32 cols)

// ---------------------------------------------------------------------------
// Scratch (device globals; no allocation allowed)
// ---------------------------------------------------------------------------
__device__ __nv_bfloat16 g_A[2][BB][2048];   // state: [hi 0..1023 | lo 1024..2047]
__device__ __nv_bfloat16 g_Wkn[2048][HH];    // Whh^T-ish: [k][n], hi then lo
__device__ __nv_bfloat16 g_Wx[1024][HH];     // Wxh: [k][n], hi then lo

// ---------------------------------------------------------------------------
// PTX helpers (family-stable: ldmatrix + mma.sync only)
// ---------------------------------------------------------------------------
__device__ __forceinline__ unsigned smem_u32(const void* p) {
    unsigned a;
    asm("{ .reg .u64 t; cvta.to.shared.u64 t, %1; cvt.u32.u64 %0, t; }"
        : "=r"(a) : "l"(p));
    return a;
}

#define LDSM4(r, a) \
    asm volatile("ldmatrix.sync.aligned.m8n8.x4.shared.b16 {%0,%1,%2,%3}, [%4];" \
        : "=r"((r)[0]), "=r"((r)[1]), "=r"((r)[2]), "=r"((r)[3]) : "r"(a))

#define LDSM4T(r, a) \
    asm volatile("ldmatrix.sync.aligned.m8n8.x4.trans.shared.b16 {%0,%1,%2,%3}, [%4];" \
        : "=r"((r)[0]), "=r"((r)[1]), "=r"((r)[2]), "=r"((r)[3]) : "r"(a))

__device__ __forceinline__ void mma16816(float* d, const unsigned* a,
                                         unsigned b0, unsigned b1) {
    asm volatile(
        "mma.sync.aligned.m16n8k16.row.col.f32.bf16.bf16.f32 "
        "{%0,%1,%2,%3}, {%4,%5,%6,%7}, {%8,%9}, {%0,%1,%2,%3};"
        : "+f"(d[0]), "+f"(d[1]), "+f"(d[2]), "+f"(d[3])
        : "r"(a[0]), "r"(a[1]), "r"(a[2]), "r"(a[3]), "r"(b0), "r"(b1));
}

// pack 8 fp32 -> uint4 hi bf16, uint4 lo bf16
__device__ __forceinline__ void split8(float4 a, float4 b, uint4& hi, uint4& lo) {
    float s[8] = {a.x, a.y, a.z, a.w, b.x, b.y, b.z, b.w};
    unsigned h[4], l[4];
    #pragma unroll
    for (int i = 0; i < 4; i++) {
        __nv_bfloat16 h0 = __float2bfloat16(s[2 * i]);
        __nv_bfloat16 h1 = __float2bfloat16(s[2 * i + 1]);
        __nv_bfloat16 l0 = __float2bfloat16(s[2 * i] - __bfloat162float(h0));
        __nv_bfloat16 l1 = __float2bfloat16(s[2 * i + 1] - __bfloat162float(h1));
        h[i] = (unsigned)__bfloat16_as_ushort(h0)
             | ((unsigned)__bfloat16_as_ushort(h1) << 16);
        l[i] = (unsigned)__bfloat16_as_ushort(l0)
             | ((unsigned)__bfloat16_as_ushort(l1) << 16);
    }
    hi = make_uint4(h[0], h[1], h[2], h[3]);
    lo = make_uint4(l[0], l[1], l[2], l[3]);
}

// ---------------------------------------------------------------------------
// Grid-wide barrier
// ---------------------------------------------------------------------------
__device__ unsigned int g_bar = 0;
__global__ void bar_reset() { g_bar = 0; }

__device__ __forceinline__ void grid_bar(unsigned target) {
    __syncthreads();
    if (threadIdx.x == 0) {
        __threadfence();
        atomicAdd(&g_bar, 1u);
        volatile unsigned* p = &g_bar;
        while (*p < target) __nanosleep(64);
        __threadfence();
    }
    __syncthreads();
}

// ---------------------------------------------------------------------------
// Prep: weight conversions + h0
// ---------------------------------------------------------------------------
__global__ void __launch_bounds__(256)
wt_convert(const float* __restrict__ Whh)
{
    int idx = blockIdx.x * 256 + threadIdx.x;
    int k = idx >> 10, n = idx & 1023;
    float w = Whh[(long)k * HH + n];
    __nv_bfloat16 hi = __float2bfloat16(w);
    __nv_bfloat16 lo = __float2bfloat16(w - __bfloat162float(hi));
    g_Wkn[k][n] = hi;
    g_Wkn[1024 + k][n] = lo;
}

__global__ void __launch_bounds__(256)
wx_convert(const float* __restrict__ Wxh)
{
    int idx = blockIdx.x * 256 + threadIdx.x;
    int k = idx >> 10, n = idx & 1023;
    float w = Wxh[(long)k * HH + n];
    __nv_bfloat16 hi = __float2bfloat16(w);
    __nv_bfloat16 lo = __float2bfloat16(w - __bfloat162float(hi));
    g_Wx[k][n] = hi;
    g_Wx[512 + k][n] = lo;
}

__global__ void __launch_bounds__(256)
init_h0(float* __restrict__ out)
{
    int idx = blockIdx.x * 256 + threadIdx.x;
    int b = idx >> 10, c = idx & 1023;
    float v = out[(long)b * LDR + c];
    v = fmaxf(v, 0.f);
    out[(long)b * LDR + c] = v;
    __nv_bfloat16 hi = __float2bfloat16(v);
    __nv_bfloat16 lo = __float2bfloat16(v - __bfloat162float(hi));
    g_A[0][b][c] = hi;
    g_A[0][b][1024 + c] = lo;
}

// ---------------------------------------------------------------------------
// Phase 1 (tensor): xh = x @ Wxh + bxh  (unchanged from round 6)
// ---------------------------------------------------------------------------
extern __shared__ char smx[];

#define AFX(kg, m) ((unsigned)((kg) * 2048 + ((m) >> 3) * 128 + ((((m) & 7) ^ (kg)) * 16)))

__global__ void __launch_bounds__(256)
gemm_xh_mma(const float* __restrict__ x,     // [131072, 512]
            const float* __restrict__ bias,  // [1024]
            float* __restrict__ C)           // [131072, 1024]
{
    const int tid  = threadIdx.x;
    const int wid  = tid >> 5;
    const int lane = tid & 31;
    const int wr   = wid & 3;
    const int wc   = wid >> 2;
    const int bm   = blockIdx.y;
    const int bn   = blockIdx.x;

    const unsigned sb = smem_u32(smx);
    const int q   = lane >> 3;
    const int l7  = lane & 7;
    const int kgq = q >> 1;

    const int am = tid & 127;
    const int wk = tid & 31;

    float2 breg[8];
    #pragma unroll
    for (int n8 = 0; n8 < 8; n8++)
        breg[n8] = *(const float2*)&bias[bn * 128 + wc * 64 + n8 * 8 + (lane & 3) * 2];

    float acc[2][8][4];
    #pragma unroll
    for (int m = 0; m < 2; m++)
        #pragma unroll
        for (int n = 0; n < 8; n++)
            #pragma unroll
            for (int j = 0; j < 4; j++) acc[m][n][j] = 0.f;

    const float* xb = x + (long)(bm * 128) * EE;

    float4 xa[2][2];
    uint4  wvh[2], wvl[2];
    #pragma unroll
    for (int i = 0; i < 2; i++) {
        int idx = tid + i * 256;
        int kg = idx >> 7;
        const float* p = xb + (long)am * EE + kg * 8;
        xa[i][0] = *(const float4*)p;
        xa[i][1] = *(const float4*)(p + 4);
        int pp = (idx >> 5) & 15;
        wvh[i] = *(const uint4*)&g_Wx[wk][bn * 128 + pp * 8];
        wvl[i] = *(const uint4*)&g_Wx[512 + wk][bn * 128 + pp * 8];
    }
    #pragma unroll
    for (int i = 0; i < 2; i++) {
        int idx = tid + i * 256;
        int kg = idx >> 7;
        uint4 hi, lo;
        split8(xa[i][0], xa[i][1], hi, lo);
        unsigned ao = AFX(kg, am);
        *(uint4*)(smx + ao)         = hi;
        *(uint4*)(smx + 8192 + ao)  = lo;
        int pp = (idx >> 5) & 15;
        unsigned wo = 16384u + (unsigned)pp * 512u + (unsigned)wk * 16u;
        *(uint4*)(smx + wo)         = wvh[i];
        *(uint4*)(smx + 8192 + wo)  = wvl[i];
    }
    __syncthreads();

    unsigned buf = 0;
    for (int kc = 0; kc < 16; kc++) {
        const bool more = (kc + 1 < 16);
        if (more) {
            const int k0 = (kc + 1) * 32;
            #pragma unroll
            for (int i = 0; i < 2; i++) {
                int idx = tid + i * 256;
                int kg = idx >> 7;
                const float* p = xb + (long)am * EE + k0 + kg * 8;
                xa[i][0] = *(const float4*)p;
                xa[i][1] = *(const float4*)(p + 4);
                int pp = (idx >> 5) & 15;
                wvh[i] = *(const uint4*)&g_Wx[k0 + wk][bn * 128 + pp * 8];
                wvl[i] = *(const uint4*)&g_Wx[512 + k0 + wk][bn * 128 + pp * 8];
            }
        }

        const unsigned B0 = sb + buf * 32768u;
        #pragma unroll
        for (int s16 = 0; s16 < 2; s16++) {
            const int kg = s16 * 2 + kgq;
            const unsigned aoff = (unsigned)kg * 2048u + (unsigned)((l7 ^ kg) * 16);
            unsigned ahi[2][4], alo[2][4];
            LDSM4(ahi[0], B0 + aoff + (unsigned)(wr * 4 + 0 + (q & 1)) * 128u);
            LDSM4(ahi[1], B0 + aoff + (unsigned)(wr * 4 + 2 + (q & 1)) * 128u);
            LDSM4(alo[0], B0 + 8192u + aoff + (unsigned)(wr * 4 + 0 + (q & 1)) * 128u);
            LDSM4(alo[1], B0 + 8192u + aoff + (unsigned)(wr * 4 + 2 + (q & 1)) * 128u);

            const unsigned wrow = (unsigned)(s16 * 16 + (q & 1) * 8 + l7) * 16u;
            #pragma unroll
            for (int pp = 0; pp < 4; pp++) {
                unsigned wh[4], wl[4];
                unsigned wbase = B0 + 16384u
                               + (unsigned)(wc * 8 + pp * 2 + kgq) * 512u + wrow;
                LDSM4T(wh, wbase);
                LDSM4T(wl, wbase + 8192u);
                const int n0 = pp * 2, n1 = pp * 2 + 1;
                mma16816(acc[0][n0], ahi[0], wh[0], wh[1]);
                mma16816(acc[0][n1], ahi[0], wh[2], wh[3]);
                mma16816(acc[1][n0], ahi[1], wh[0], wh[1]);
                mma16816(acc[1][n1], ahi[1], wh[2], wh[3]);
                mma16816(acc[0][n0], alo[0], wh[0], wh[1]);
                mma16816(acc[0][n1], alo[0], wh[2], wh[3]);
                mma16816(acc[1][n0], alo[1], wh[0], wh[1]);
                mma16816(acc[1][n1], alo[1], wh[2], wh[3]);
                mma16816(acc[0][n0], ahi[0], wl[0], wl[1]);
                mma16816(acc[0][n1], ahi[0], wl[2], wl[3]);
                mma16816(acc[1][n0], ahi[1], wl[0], wl[1]);
                mma16816(acc[1][n1], ahi[1], wl[2], wl[3]);
            }
        }

        if (more) {
            const unsigned nb = (buf ^ 1u) * 32768u;
            #pragma unroll
            for (int i = 0; i < 2; i++) {
                int idx = tid + i * 256;
                int kg = idx >> 7;
                uint4 hi, lo;
                split8(xa[i][0], xa[i][1], hi, lo);
                unsigned ao = nb + AFX(kg, am);
                *(uint4*)(smx + ao)        = hi;
                *(uint4*)(smx + 8192 + ao) = lo;
                int pp = (idx >> 5) & 15;
                unsigned wo = nb + 16384u + (unsigned)pp * 512u + (unsigned)wk * 16u;
                *(uint4*)(smx + wo)        = wvh[i];
                *(uint4*)(smx + 8192 + wo) = wvl[i];
            }
            __syncthreads();
            buf ^= 1u;
        }
    }

    #pragma unroll
    for (int mm = 0; mm < 2; mm++) {
        #pragma unroll
        for (int half = 0; half < 2; half++) {
            long row = (long)bm * 128 + wr * 32 + mm * 16 + (lane >> 2) + half * 8;
            float* pr = C + row * HH + bn * 128 + wc * 64 + (lane & 3) * 2;
            #pragma unroll
            for (int n8 = 0; n8 < 8; n8++) {
                float2 o;
                o.x = acc[mm][n8][half * 2 + 0] + breg[n8].x;
                o.y = acc[mm][n8][half * 2 + 1] + breg[n8].y;
                *(float2*)(pr + n8 * 8) = o;
            }
        }
    }
}

// ---------------------------------------------------------------------------
// Phase 2: persistent mma.sync scan — k-split warps.
// CTA: 64m x 32n tile. 8 warps = 2 m-halves (wm: 32 rows) x 4 k-quarters (kq).
// Per chunk (256 packed cols = 128 hi k + 128 lo k), 24 k16-granule products
// (8 AhiWhi + 8 AhiWlo + 8 AloWhi) are split 6 per k-warp; hi-product pairs
// share one A fragment. Warp accumulates a 32x32 fp32 partial; k-reduction
// via smem (reuses A buffer 0) + coalesced epilogue.
// W resident in smem (once): hi @64KB, lo @128KB; 4 panels [1024k][8n].
// A chunks double-buffered at 0 with XOR-swizzled 16B slots.
// ---------------------------------------------------------------------------
#define AF(kg, r) ((unsigned)((kg) * 1024 + ((r) >> 3) * 128 + ((((r) & 7) ^ ((kg) & 7)) * 16)))

__global__ void __launch_bounds__(256, 1)
rnn_scan_mma(float* __restrict__ out)
{
    const int tid  = threadIdx.x;
    const int wid  = tid >> 5;
    const int lane = tid & 31;
    const int wm   = wid & 1;           // m-half: rows wm*32 .. +32
    const int kq   = wid >> 1;          // k-quarter 0..3
    const int bm   = blockIdx.x >> 5;   // 0..3
    const int bn   = blockIdx.x & 31;   // 0..31

    const unsigned sb = smem_u32(smx);

    // ---- stage W slice into SMEM panels (once) ----
    for (int i = 0; i < 32; i++) {
        int kk = i * 64 + (tid >> 2);      // 0..2047 packed k
        int p  = tid & 3;                  // n8 panel
        uint4 v = *(const uint4*)&g_Wkn[kk][bn * 32 + p * 8];
        unsigned off = 65536u + (unsigned)(kk >> 10) * 65536u
                     + (unsigned)p * 16384u + (unsigned)(kk & 1023) * 16u;
        *(uint4*)(smx + off) = v;
    }
    __syncthreads();

    // ldmatrix lane addressing
    const int q   = lane >> 3;
    const int l7  = lane & 7;
    const int kgq = q >> 1;
    // A line base for m16 tile mi of this warp's m-half
    const unsigned lineA0 = (unsigned)(wm * 4 + 0 + (q & 1)) * 128u;
    const unsigned lineA1 = (unsigned)(wm * 4 + 2 + (q & 1)) * 128u;
    // W: panel pair selected by q>>1; +32768 for panels 2,3 (n16..31)
    const unsigned wrowsel = (unsigned)((q & 1) * 8 + l7) * 16u;
    const unsigned whiBase = sb + 65536u + (unsigned)(q >> 1) * 16384u + wrowsel;
    const unsigned wloBase = whiBase + 65536u;

    // A staging mapping (LDG/STS)
    const int rs2 = tid >> 4;           // 0..15
    const int kg2 = tid & 15;           // 0..15

    // partial-store / epilogue mapping
    const int eg = lane >> 2;           // 0..7
    const int ei = lane & 3;            // 0..3
    const int r64 = tid >> 2;           // 0..63
    const int n0  = (tid & 3) * 8;      // 0,8,16,24
    const int wmE = r64 >> 5;
    const int rE  = r64 & 31;

    unsigned nbar = 0;

    for (int t = 1; t < TT; t++) {
        const __nv_bfloat16* Ar = &g_A[(t + 1) & 1][bm * 64][0];

        float d[2][4][4];                // [mi][n8 tile][frag]
        #pragma unroll
        for (int mi = 0; mi < 2; mi++)
            #pragma unroll
            for (int nt = 0; nt < 4; nt++)
                #pragma unroll
                for (int j = 0; j < 4; j++) d[mi][nt][j] = 0.f;

        uint4 v[8];

        // prefetch + stage chunk 0
        #pragma unroll
        for (int i = 0; i < 4; i++) {
            int r = rs2 + i * 16;
            const __nv_bfloat16* p = Ar + (long)r * 2048 + kg2 * 8;
            v[i * 2 + 0] = *(const uint4*)(p);
            v[i * 2 + 1] = *(const uint4*)(p + 1024);
        }
        #pragma unroll
        for (int i = 0; i < 4; i++) {
            int r = rs2 + i * 16;
            unsigned o1 = AF(kg2, r);
            *(uint4*)(smx + o1)          = v[i * 2 + 0];
            *(uint4*)(smx + 16384u + o1) = v[i * 2 + 1];
        }
        __syncthreads();

        for (int c = 0; c < 8; c++) {
            const bool more = (c + 1 < 8);
            if (more) {
                #pragma unroll
                for (int i = 0; i < 4; i++) {
                    int r = rs2 + i * 16;
                    const __nv_bfloat16* p = Ar + (long)r * 2048 + (c + 1) * 128 + kg2 * 8;
                    v[i * 2 + 0] = *(const uint4*)(p);
                    v[i * 2 + 1] = *(const uint4*)(p + 1024);
                }
            }

            const unsigned B0 = sb + (unsigned)(c & 1) * 32768u;
            const unsigned wko = (unsigned)(c * 8) * 256u;   // W k16 base for chunk

            // 3 product-slots of 2 for this k-warp
            #pragma unroll
            for (int s2 = 0; s2 < 3; s2++) {
                const int p = kq * 6 + s2 * 2;
                if (p < 16) {
                    // paired hi products: A hi g, W hi + W lo
                    const int g = p >> 1;
                    const int kg = 2 * g + kgq;
                    const unsigned aoff = (unsigned)kg * 1024u
                                        + (unsigned)((l7 ^ (kg & 7)) * 16);
                    unsigned a0[4], a1[4], wh1[4], wh2[4], wl1[4], wl2[4];
                    LDSM4(a0, B0 + lineA0 + aoff);
                    LDSM4(a1, B0 + lineA1 + aoff);
                    const unsigned wo = wko + (unsigned)g * 256u;
                    LDSM4T(wh1, whiBase + wo);
                    LDSM4T(wh2, whiBase + 32768u + wo);
                    LDSM4T(wl1, wloBase + wo);
                    LDSM4T(wl2, wloBase + 32768u + wo);

                    mma16816(d[0][0], a0, wh1[0], wh1[1]);
                    mma16816(d[0][1], a0, wh1[2], wh1[3]);
                    mma16816(d[0][2], a0, wh2[0], wh2[1]);
                    mma16816(d[0][3], a0, wh2[2], wh2[3]);
                    mma16816(d[1][0], a1, wh1[0], wh1[1]);
                    mma16816(d[1][1], a1, wh1[2], wh1[3]);
                    mma16816(d[1][2], a1, wh2[0], wh2[1]);
                    mma16816(d[1][3], a1, wh2[2], wh2[3]);
                    mma16816(d[0][0], a0, wl1[0], wl1[1]);
                    mma16816(d[0][1], a0, wl1[2], wl1[3]);
                    mma16816(d[0][2], a0, wl2[0], wl2[1]);
                    mma16816(d[0][3], a0, wl2[2], wl2[3]);
                    mma16816(d[1][0], a1, wl1[0], wl1[1]);
                    mma16816(d[1][1], a1, wl1[2], wl1[3]);
                    mma16816(d[1][2], a1, wl2[0], wl2[1]);
                    mma16816(d[1][3], a1, wl2[2], wl2[3]);
                } else {
                    // two lo products: A lo g, W hi
                    #pragma unroll
                    for (int u = 0; u < 2; u++) {
                        const int g = p + u - 16;
                        const int kg = 2 * g + kgq;
                        const unsigned aoff = 16384u + (unsigned)kg * 1024u
                                            + (unsigned)((l7 ^ (kg & 7)) * 16);
                        unsigned a0[4], a1[4], wh1[4], wh2[4];
                        LDSM4(a0, B0 + lineA0 + aoff);
                        LDSM4(a1, B0 + lineA1 + aoff);
                        const unsigned wo = wko + (unsigned)g * 256u;
                        LDSM4T(wh1, whiBase + wo);
                        LDSM4T(wh2, whiBase + 32768u + wo);

                        mma16816(d[0][0], a0, wh1[0], wh1[1]);
                        mma16816(d[0][1], a0, wh1[2], wh1[3]);
                        mma16816(d[0][2], a0, wh2[0], wh2[1]);
                        mma16816(d[0][3], a0, wh2[2], wh2[3]);
                        mma16816(d[1][0], a1, wh1[0], wh1[1]);
                        mma16816(d[1][1], a1, wh1[2], wh1[3]);
                        mma16816(d[1][2], a1, wh2[0], wh2[1]);
                        mma16816(d[1][3], a1, wh2[2], wh2[3]);
                    }
                }
            }

            if (more) {
                const unsigned B1 = (unsigned)((c + 1) & 1) * 32768u;
                #pragma unroll
                for (int i = 0; i < 4; i++) {
                    int r = rs2 + i * 16;
                    unsigned o1 = B1 + AF(kg2, r);
                    *(uint4*)(smx + o1)          = v[i * 2 + 0];
                    *(uint4*)(smx + 16384u + o1) = v[i * 2 + 1];
                }
                __syncthreads();
            }
        }

        // ---- k-reduction: store 32x32 fp32 partials into buffer 0 region ----
        {
            const unsigned pb = (unsigned)((wm * 4 + kq) * 4096);
            #pragma unroll
            for (int mi = 0; mi < 2; mi++) {
                #pragma unroll
                for (int half = 0; half < 2; half++) {
                    const int r = mi * 16 + eg + half * 8;   // 0..31
                    #pragma unroll
                    for (int nt = 0; nt < 4; nt++) {
                        float2 pv;
                        pv.x = d[mi][nt][half * 2 + 0];
                        pv.y = d[mi][nt][half * 2 + 1];
                        *(float2*)(smx + pb + (unsigned)r * 128u
                                   + (unsigned)(nt * 8 + 2 * ei) * 4u) = pv;
                    }
                }
            }
        }
        __syncthreads();

        // ---- reduce 4 partials + epilogue (coalesced) ----
        {
            float4 s0 = {0.f, 0.f, 0.f, 0.f}, s1 = {0.f, 0.f, 0.f, 0.f};
            #pragma unroll
            for (int k4 = 0; k4 < 4; k4++) {
                const float* pp = (const float*)(smx
                    + (unsigned)((wmE * 4 + k4) * 4096)
                    + (unsigned)rE * 128u + (unsigned)n0 * 4u);
                float4 a = *(const float4*)pp;
                float4 b = *(const float4*)(pp + 4);
                s0.x += a.x; s0.y += a.y; s0.z += a.z; s0.w += a.w;
                s1.x += b.x; s1.y += b.y; s1.z += b.z; s1.w += b.w;
            }

            const int gb = bm * 64 + r64;
            float* po = out + (long)gb * LDR + (long)t * HH + bn * 32 + n0;
            float4 x0 = *(const float4*)po;
            float4 x1 = *(const float4*)(po + 4);
            float4 o0, o1;
            o0.x = fmaxf(x0.x + s0.x, 0.f); o0.y = fmaxf(x0.y + s0.y, 0.f);
            o0.z = fmaxf(x0.z + s0.z, 0.f); o0.w = fmaxf(x0.w + s0.w, 0.f);
            o1.x = fmaxf(x1.x + s1.x, 0.f); o1.y = fmaxf(x1.y + s1.y, 0.f);
            o1.z = fmaxf(x1.z + s1.z, 0.f); o1.w = fmaxf(x1.w + s1.w, 0.f);
            *(float4*)po = o0;
            *(float4*)(po + 4) = o1;

            uint4 hi, lo;
            split8(o0, o1, hi, lo);
            __nv_bfloat16* pa = &g_A[t & 1][gb][0];
            const int ccol = bn * 32 + n0;
            *(uint4*)(pa + ccol)        = hi;
            *(uint4*)(pa + 1024 + ccol) = lo;
        }

        if (t < TT - 1) {
            nbar++;
            grid_bar(nbar * NCTA);
        }
    }
}

// ---------------------------------------------------------------------------
extern "C" void kernel_launch(void* const* d_in, const int* in_sizes, int n_in,
                              void* d_out, int out_size)
{
    const float* x   = (const float*)d_in[0];   // [256,512,512]
    const float* Wxh = (const float*)d_in[1];   // [512,1024]
    const float* bxh = (const float*)d_in[2];   // [1024]
    const float* Whh = (const float*)d_in[3];   // [1024,1024]
    float* out = (float*)d_out;                 // [256,512,1024]

    // Prep: weight splits
    wx_convert<<<(EE * HH) / 256, 256>>>(Wxh);
    wt_convert<<<(HH * HH) / 256, 256>>>(Whh);

    // Phase 1: xh -> d_out (tensor cores, bf16 hi/lo x3)
    const int smem_p1 = 2 * 32768;
    cudaFuncSetAttribute(gemm_xh_mma,
                         cudaFuncAttributeMaxDynamicSharedMemorySize, smem_p1);
    dim3 g1(HH / 128, (BB * TT) / 128);          // (8, 1024)
    gemm_xh_mma<<<g1, 256, smem_p1>>>(x, bxh, out);

    // h0 = relu(xh_0) + bf16 split
    init_h0<<<(BB * HH) / 256, 256>>>(out);

    // Phase 2: persistent mma.sync scan (k-split warps)
    const int smem_p2 = 65536 + 2 * 65536;       // A dbl 64KB + W 128KB
    cudaFuncSetAttribute(rnn_scan_mma,
                         cudaFuncAttributeMaxDynamicSharedMemorySize, smem_p2);
    rnn_scan_mma<<<NCTA, 256, smem_p2>>>(out);

    // reset grid barrier for next replay
    bar_reset<<<1, 1>>>();
}

// round 8
// speedup vs baseline: 3.6157x; 1.0451x over previous
#include <cuda_runtime.h>
#include <cuda_bf16.h>

// Problem dims (fixed by the reference)
#define BB   256      // batch
#define TT   512      // timesteps
#define EE   512      // input dim
#define HH   1024     // hidden dim
#define LDR  ((long)TT * HH)   // row stride between batches in d_out

#define NCTA 128      // persistent CTAs: 4 M-tiles (64 rows) x 32 N-tiles (32 cols)

// ---------------------------------------------------------------------------
// Scratch (device globals; no allocation allowed)
// ---------------------------------------------------------------------------
__device__ __nv_bfloat16 g_A[2][BB][2048];   // state: [hi 0..1023 | lo 1024..2047]
__device__ __nv_bfloat16 g_Wkn[2048][HH];    // Whh: [k][n], hi rows 0..1023, lo 1024..2047
__device__ __nv_bfloat16 g_Wx[1024][HH];     // Wxh: [k][n], hi then lo

// ---------------------------------------------------------------------------
// PTX helpers (family-stable: ldmatrix + mma.sync only)
// ---------------------------------------------------------------------------
__device__ __forceinline__ unsigned smem_u32(const void* p) {
    unsigned a;
    asm("{ .reg .u64 t; cvta.to.shared.u64 t, %1; cvt.u32.u64 %0, t; }"
        : "=r"(a) : "l"(p));
    return a;
}

#define LDSM4(r, a) \
    asm volatile("ldmatrix.sync.aligned.m8n8.x4.shared.b16 {%0,%1,%2,%3}, [%4];" \
        : "=r"((r)[0]), "=r"((r)[1]), "=r"((r)[2]), "=r"((r)[3]) : "r"(a))

#define LDSM4T(r, a) \
    asm volatile("ldmatrix.sync.aligned.m8n8.x4.trans.shared.b16 {%0,%1,%2,%3}, [%4];" \
        : "=r"((r)[0]), "=r"((r)[1]), "=r"((r)[2]), "=r"((r)[3]) : "r"(a))

__device__ __forceinline__ void mma16816(float* d, const unsigned* a,
                                         unsigned b0, unsigned b1) {
    asm volatile(
        "mma.sync.aligned.m16n8k16.row.col.f32.bf16.bf16.f32 "
        "{%0,%1,%2,%3}, {%4,%5,%6,%7}, {%8,%9}, {%0,%1,%2,%3};"
        : "+f"(d[0]), "+f"(d[1]), "+f"(d[2]), "+f"(d[3])
        : "r"(a[0]), "r"(a[1]), "r"(a[2]), "r"(a[3]), "r"(b0), "r"(b1));
}

// pack 8 fp32 -> uint4 hi bf16, uint4 lo bf16
__device__ __forceinline__ void split8(float4 a, float4 b, uint4& hi, uint4& lo) {
    float s[8] = {a.x, a.y, a.z, a.w, b.x, b.y, b.z, b.w};
    unsigned h[4], l[4];
    #pragma unroll
    for (int i = 0; i < 4; i++) {
        __nv_bfloat16 h0 = __float2bfloat16(s[2 * i]);
        __nv_bfloat16 h1 = __float2bfloat16(s[2 * i + 1]);
        __nv_bfloat16 l0 = __float2bfloat16(s[2 * i] - __bfloat162float(h0));
        __nv_bfloat16 l1 = __float2bfloat16(s[2 * i + 1] - __bfloat162float(h1));
        h[i] = (unsigned)__bfloat16_as_ushort(h0)
             | ((unsigned)__bfloat16_as_ushort(h1) << 16);
        l[i] = (unsigned)__bfloat16_as_ushort(l0)
             | ((unsigned)__bfloat16_as_ushort(l1) << 16);
    }
    hi = make_uint4(h[0], h[1], h[2], h[3]);
    lo = make_uint4(l[0], l[1], l[2], l[3]);
}

// ---------------------------------------------------------------------------
// Grid-wide barrier
// ---------------------------------------------------------------------------
__device__ unsigned int g_bar = 0;
__global__ void bar_reset() { g_bar = 0; }

__device__ __forceinline__ void grid_bar(unsigned target) {
    __syncthreads();
    if (threadIdx.x == 0) {
        __threadfence();
        atomicAdd(&g_bar, 1u);
        volatile unsigned* p = &g_bar;
        while (*p < target) __nanosleep(64);
        __threadfence();
    }
    __syncthreads();
}

// ---------------------------------------------------------------------------
// Prep: weight conversions + h0
// ---------------------------------------------------------------------------
__global__ void __launch_bounds__(256)
wt_convert(const float* __restrict__ Whh)
{
    int idx = blockIdx.x * 256 + threadIdx.x;
    int k = idx >> 10, n = idx & 1023;
    float w = Whh[(long)k * HH + n];
    __nv_bfloat16 hi = __float2bfloat16(w);
    __nv_bfloat16 lo = __float2bfloat16(w - __bfloat162float(hi));
    g_Wkn[k][n] = hi;
    g_Wkn[1024 + k][n] = lo;
}

__global__ void __launch_bounds__(256)
wx_convert(const float* __restrict__ Wxh)
{
    int idx = blockIdx.x * 256 + threadIdx.x;
    int k = idx >> 10, n = idx & 1023;
    float w = Wxh[(long)k * HH + n];
    __nv_bfloat16 hi = __float2bfloat16(w);
    __nv_bfloat16 lo = __float2bfloat16(w - __bfloat162float(hi));
    g_Wx[k][n] = hi;
    g_Wx[512 + k][n] = lo;
}

__global__ void __launch_bounds__(256)
init_h0(float* __restrict__ out)
{
    int idx = blockIdx.x * 256 + threadIdx.x;
    int b = idx >> 10, c = idx & 1023;
    float v = out[(long)b * LDR + c];
    v = fmaxf(v, 0.f);
    out[(long)b * LDR + c] = v;
    __nv_bfloat16 hi = __float2bfloat16(v);
    __nv_bfloat16 lo = __float2bfloat16(v - __bfloat162float(hi));
    g_A[0][b][c] = hi;
    g_A[0][b][1024 + c] = lo;
}

// ---------------------------------------------------------------------------
// Phase 1 (tensor): xh = x @ Wxh + bxh  (unchanged from round 6/7)
// ---------------------------------------------------------------------------
extern __shared__ char smx[];

#define AFX(kg, m) ((unsigned)((kg) * 2048 + ((m) >> 3) * 128 + ((((m) & 7) ^ (kg)) * 16)))

__global__ void __launch_bounds__(256)
gemm_xh_mma(const float* __restrict__ x,     // [131072, 512]
            const float* __restrict__ bias,  // [1024]
            float* __restrict__ C)           // [131072, 1024]
{
    const int tid  = threadIdx.x;
    const int wid  = tid >> 5;
    const int lane = tid & 31;
    const int wr   = wid & 3;
    const int wc   = wid >> 2;
    const int bm   = blockIdx.y;
    const int bn   = blockIdx.x;

    const unsigned sb = smem_u32(smx);
    const int q   = lane >> 3;
    const int l7  = lane & 7;
    const int kgq = q >> 1;

    const int am = tid & 127;
    const int wk = tid & 31;

    float2 breg[8];
    #pragma unroll
    for (int n8 = 0; n8 < 8; n8++)
        breg[n8] = *(const float2*)&bias[bn * 128 + wc * 64 + n8 * 8 + (lane & 3) * 2];

    float acc[2][8][4];
    #pragma unroll
    for (int m = 0; m < 2; m++)
        #pragma unroll
        for (int n = 0; n < 8; n++)
            #pragma unroll
            for (int j = 0; j < 4; j++) acc[m][n][j] = 0.f;

    const float* xb = x + (long)(bm * 128) * EE;

    float4 xa[2][2];
    uint4  wvh[2], wvl[2];
    #pragma unroll
    for (int i = 0; i < 2; i++) {
        int idx = tid + i * 256;
        int kg = idx >> 7;
        const float* p = xb + (long)am * EE + kg * 8;
        xa[i][0] = *(const float4*)p;
        xa[i][1] = *(const float4*)(p + 4);
        int pp = (idx >> 5) & 15;
        wvh[i] = *(const uint4*)&g_Wx[wk][bn * 128 + pp * 8];
        wvl[i] = *(const uint4*)&g_Wx[512 + wk][bn * 128 + pp * 8];
    }
    #pragma unroll
    for (int i = 0; i < 2; i++) {
        int idx = tid + i * 256;
        int kg = idx >> 7;
        uint4 hi, lo;
        split8(xa[i][0], xa[i][1], hi, lo);
        unsigned ao = AFX(kg, am);
        *(uint4*)(smx + ao)         = hi;
        *(uint4*)(smx + 8192 + ao)  = lo;
        int pp = (idx >> 5) & 15;
        unsigned wo = 16384u + (unsigned)pp * 512u + (unsigned)wk * 16u;
        *(uint4*)(smx + wo)         = wvh[i];
        *(uint4*)(smx + 8192 + wo)  = wvl[i];
    }
    __syncthreads();

    unsigned buf = 0;
    for (int kc = 0; kc < 16; kc++) {
        const bool more = (kc + 1 < 16);
        if (more) {
            const int k0 = (kc + 1) * 32;
            #pragma unroll
            for (int i = 0; i < 2; i++) {
                int idx = tid + i * 256;
                int kg = idx >> 7;
                const float* p = xb + (long)am * EE + k0 + kg * 8;
                xa[i][0] = *(const float4*)p;
                xa[i][1] = *(const float4*)(p + 4);
                int pp = (idx >> 5) & 15;
                wvh[i] = *(const uint4*)&g_Wx[k0 + wk][bn * 128 + pp * 8];
                wvl[i] = *(const uint4*)&g_Wx[512 + k0 + wk][bn * 128 + pp * 8];
            }
        }

        const unsigned B0 = sb + buf * 32768u;
        #pragma unroll
        for (int s16 = 0; s16 < 2; s16++) {
            const int kg = s16 * 2 + kgq;
            const unsigned aoff = (unsigned)kg * 2048u + (unsigned)((l7 ^ kg) * 16);
            unsigned ahi[2][4], alo[2][4];
            LDSM4(ahi[0], B0 + aoff + (unsigned)(wr * 4 + 0 + (q & 1)) * 128u);
            LDSM4(ahi[1], B0 + aoff + (unsigned)(wr * 4 + 2 + (q & 1)) * 128u);
            LDSM4(alo[0], B0 + 8192u + aoff + (unsigned)(wr * 4 + 0 + (q & 1)) * 128u);
            LDSM4(alo[1], B0 + 8192u + aoff + (unsigned)(wr * 4 + 2 + (q & 1)) * 128u);

            const unsigned wrow = (unsigned)(s16 * 16 + (q & 1) * 8 + l7) * 16u;
            #pragma unroll
            for (int pp = 0; pp < 4; pp++) {
                unsigned wh[4], wl[4];
                unsigned wbase = B0 + 16384u
                               + (unsigned)(wc * 8 + pp * 2 + kgq) * 512u + wrow;
                LDSM4T(wh, wbase);
                LDSM4T(wl, wbase + 8192u);
                const int n0 = pp * 2, n1 = pp * 2 + 1;
                mma16816(acc[0][n0], ahi[0], wh[0], wh[1]);
                mma16816(acc[0][n1], ahi[0], wh[2], wh[3]);
                mma16816(acc[1][n0], ahi[1], wh[0], wh[1]);
                mma16816(acc[1][n1], ahi[1], wh[2], wh[3]);
                mma16816(acc[0][n0], alo[0], wh[0], wh[1]);
                mma16816(acc[0][n1], alo[0], wh[2], wh[3]);
                mma16816(acc[1][n0], alo[1], wh[0], wh[1]);
                mma16816(acc[1][n1], alo[1], wh[2], wh[3]);
                mma16816(acc[0][n0], ahi[0], wl[0], wl[1]);
                mma16816(acc[0][n1], ahi[0], wl[2], wl[3]);
                mma16816(acc[1][n0], ahi[1], wl[0], wl[1]);
                mma16816(acc[1][n1], ahi[1], wl[2], wl[3]);
            }
        }

        if (more) {
            const unsigned nb = (buf ^ 1u) * 32768u;
            #pragma unroll
            for (int i = 0; i < 2; i++) {
                int idx = tid + i * 256;
                int kg = idx >> 7;
                uint4 hi, lo;
                split8(xa[i][0], xa[i][1], hi, lo);
                unsigned ao = nb + AFX(kg, am);
                *(uint4*)(smx + ao)        = hi;
                *(uint4*)(smx + 8192 + ao) = lo;
                int pp = (idx >> 5) & 15;
                unsigned wo = nb + 16384u + (unsigned)pp * 512u + (unsigned)wk * 16u;
                *(uint4*)(smx + wo)        = wvh[i];
                *(uint4*)(smx + 8192 + wo) = wvl[i];
            }
            __syncthreads();
            buf ^= 1u;
        }
    }

    #pragma unroll
    for (int mm = 0; mm < 2; mm++) {
        #pragma unroll
        for (int half = 0; half < 2; half++) {
            long row = (long)bm * 128 + wr * 32 + mm * 16 + (lane >> 2) + half * 8;
            float* pr = C + row * HH + bn * 128 + wc * 64 + (lane & 3) * 2;
            #pragma unroll
            for (int n8 = 0; n8 < 8; n8++) {
                float2 o;
                o.x = acc[mm][n8][half * 2 + 0] + breg[n8].x;
                o.y = acc[mm][n8][half * 2 + 1] + breg[n8].y;
                *(float2*)(pr + n8 * 8) = o;
            }
        }
    }
}

// ---------------------------------------------------------------------------
// Phase 2: persistent mma.sync scan — granule-triple fusion.
// CTA: 64m x 32n tile, 8 warps. Warp kq owns, for each chunk c, the FULL
// triple of its k16-granule g=kq: {Ahi*Whi, Ahi*Wlo, Alo*Whi} at m64 x n32.
// Loads/warp/chunk: Ahi 4 + Alo 4 + Whi 2 + Wlo 2 = 12 LDSM4 (24KB) for
// 48 MMA -> 512B/MMA (crossbar-optimal at this tile). Warp accumulates a
// 64x32 fp32 partial over all chunks; k-reduction of the 8 partials via
// XOR-swizzled smem (overlaid on A buffers) + coalesced fused epilogue.
// W resident in smem (once): hi @64KB, lo @128KB; 4 panels [1024k][8n].
// A chunks double-buffered at 0 with XOR-swizzled 16B slots.
// ---------------------------------------------------------------------------
#define AF(kg, r) ((unsigned)((kg) * 1024 + ((r) >> 3) * 128 + ((((r) & 7) ^ ((kg) & 7)) * 16)))

__global__ void __launch_bounds__(256, 1)
rnn_scan_mma(float* __restrict__ out)
{
    const int tid  = threadIdx.x;
    const int kq   = tid >> 5;          // warp = k16-granule owner 0..7
    const int lane = tid & 31;
    const int bm   = blockIdx.x >> 5;   // 0..3
    const int bn   = blockIdx.x & 31;   // 0..31

    const unsigned sb = smem_u32(smx);

    // ---- stage W slice into SMEM panels (once) ----
    for (int i = 0; i < 32; i++) {
        int kk = i * 64 + (tid >> 2);      // 0..2047 packed k
        int p  = tid & 3;                  // n8 panel
        uint4 v = *(const uint4*)&g_Wkn[kk][bn * 32 + p * 8];
        unsigned off = 65536u + (unsigned)(kk >> 10) * 65536u
                     + (unsigned)p * 16384u + (unsigned)(kk & 1023) * 16u;
        *(uint4*)(smx + off) = v;
    }
    __syncthreads();

    // ldmatrix lane addressing
    const int q   = lane >> 3;
    const int l7  = lane & 7;
    const int kgq = q >> 1;
    const int kgA = 2 * kq + kgq;          // A 8-col group for this granule
    const unsigned aoffHi = (unsigned)kgA * 1024u
                          + (unsigned)((l7 ^ (kgA & 7)) * 16);
    const unsigned aoffLo = 16384u + aoffHi;
    // A line base for m16 tile mi: rows mi*16 + (q&1)*8 + l7
    // W: panel selected by q>>1 (+32768 for n16..31)
    const unsigned wrowsel = (unsigned)((q & 1) * 8 + l7) * 16u;
    const unsigned whiBase = sb + 65536u + (unsigned)kgq * 16384u + wrowsel;
    const unsigned wloBase = whiBase + 65536u;

    // A staging mapping (LDG/STS)
    const int rs2 = tid >> 4;           // 0..15
    const int kg2 = tid & 15;           // 0..15

    // partial-store mapping
    const int eg = lane >> 2;           // 0..7
    const int ei = lane & 3;            // 0..3
    // reduction / epilogue mapping
    const int r64 = tid >> 2;           // 0..63
    const int n0  = (tid & 3) * 8;      // 0,8,16,24

    unsigned nbar = 0;

    for (int t = 1; t < TT; t++) {
        const __nv_bfloat16* Ar = &g_A[(t + 1) & 1][bm * 64][0];

        float d[4][4][4];                // [mi][n8][frag]
        #pragma unroll
        for (int mi = 0; mi < 4; mi++)
            #pragma unroll
            for (int nt = 0; nt < 4; nt++)
                #pragma unroll
                for (int j = 0; j < 4; j++) d[mi][nt][j] = 0.f;

        uint4 v[8];

        // prefetch + stage chunk 0
        #pragma unroll
        for (int i = 0; i < 4; i++) {
            int r = rs2 + i * 16;
            const __nv_bfloat16* p = Ar + (long)r * 2048 + kg2 * 8;
            v[i * 2 + 0] = *(const uint4*)(p);
            v[i * 2 + 1] = *(const uint4*)(p + 1024);
        }
        #pragma unroll
        for (int i = 0; i < 4; i++) {
            int r = rs2 + i * 16;
            unsigned o1 = AF(kg2, r);
            *(uint4*)(smx + o1)          = v[i * 2 + 0];
            *(uint4*)(smx + 16384u + o1) = v[i * 2 + 1];
        }
        __syncthreads();

        for (int c = 0; c < 8; c++) {
            const bool more = (c + 1 < 8);
            if (more) {
                #pragma unroll
                for (int i = 0; i < 4; i++) {
                    int r = rs2 + i * 16;
                    const __nv_bfloat16* p = Ar + (long)r * 2048 + (c + 1) * 128 + kg2 * 8;
                    v[i * 2 + 0] = *(const uint4*)(p);
                    v[i * 2 + 1] = *(const uint4*)(p + 1024);
                }
            }

            const unsigned B0 = sb + (unsigned)(c & 1) * 32768u;
            const unsigned wko = (unsigned)(c * 8 + kq) * 256u;  // this granule's W rows

            // W fragments for the whole triple (loaded once)
            unsigned wh1[4], wh2[4], wl1[4], wl2[4];
            LDSM4T(wh1, whiBase + wko);
            LDSM4T(wh2, whiBase + 32768u + wko);
            LDSM4T(wl1, wloBase + wko);
            LDSM4T(wl2, wloBase + 32768u + wko);

            #pragma unroll
            for (int mi = 0; mi < 4; mi++) {
                const unsigned line = (unsigned)(mi * 2 + (q & 1)) * 128u;
                unsigned ahi[4], alo[4];
                LDSM4(ahi, B0 + line + aoffHi);
                // Ahi x Whi + Ahi x Wlo (8 MMA per A frag)
                mma16816(d[mi][0], ahi, wh1[0], wh1[1]);
                mma16816(d[mi][1], ahi, wh1[2], wh1[3]);
                mma16816(d[mi][2], ahi, wh2[0], wh2[1]);
                mma16816(d[mi][3], ahi, wh2[2], wh2[3]);
                mma16816(d[mi][0], ahi, wl1[0], wl1[1]);
                mma16816(d[mi][1], ahi, wl1[2], wl1[3]);
                mma16816(d[mi][2], ahi, wl2[0], wl2[1]);
                mma16816(d[mi][3], ahi, wl2[2], wl2[3]);
                // Alo x Whi (4 MMA)
                LDSM4(alo, B0 + line + aoffLo);
                mma16816(d[mi][0], alo, wh1[0], wh1[1]);
                mma16816(d[mi][1], alo, wh1[2], wh1[3]);
                mma16816(d[mi][2], alo, wh2[0], wh2[1]);
                mma16816(d[mi][3], alo, wh2[2], wh2[3]);
            }

            if (more) {
                const unsigned B1 = (unsigned)((c + 1) & 1) * 32768u;
                #pragma unroll
                for (int i = 0; i < 4; i++) {
                    int r = rs2 + i * 16;
                    unsigned o1 = B1 + AF(kg2, r);
                    *(uint4*)(smx + o1)          = v[i * 2 + 0];
                    *(uint4*)(smx + 16384u + o1) = v[i * 2 + 1];
                }
                __syncthreads();
            }
        }

        // all warps done reading A buffers before partials overwrite them
        __syncthreads();

        // ---- store 64x32 fp32 partial (XOR-16 swizzle on rows) ----
        {
            const unsigned pb = (unsigned)(kq * 8192);
            #pragma unroll
            for (int mi = 0; mi < 4; mi++) {
                #pragma unroll
                for (int half = 0; half < 2; half++) {
                    const int r = mi * 16 + eg + half * 8;   // 0..63
                    const unsigned xr = (unsigned)((r & 7) * 16);
                    #pragma unroll
                    for (int nt = 0; nt < 4; nt++) {
                        float2 pv;
                        pv.x = d[mi][nt][half * 2 + 0];
                        pv.y = d[mi][nt][half * 2 + 1];
                        unsigned cb = (unsigned)(nt * 32 + ei * 8) ^ xr;
                        *(float2*)(smx + pb + (unsigned)r * 128u + cb) = pv;
                    }
                }
            }
        }
        __syncthreads();

        // ---- reduce 8 partials + fused epilogue (coalesced) ----
        {
            const unsigned xr = (unsigned)((r64 & 7) * 16);
            const unsigned c0 = ((unsigned)(n0 * 4)) ^ xr;
            const unsigned c1 = ((unsigned)(n0 * 4 + 16)) ^ xr;
            float4 s0 = {0.f, 0.f, 0.f, 0.f}, s1 = {0.f, 0.f, 0.f, 0.f};
            #pragma unroll
            for (int p = 0; p < 8; p++) {
                const char* pp = smx + (unsigned)(p * 8192) + (unsigned)r64 * 128u;
                float4 a = *(const float4*)(pp + c0);
                float4 b = *(const float4*)(pp + c1);
                s0.x += a.x; s0.y += a.y; s0.z += a.z; s0.w += a.w;
                s1.x += b.x; s1.y += b.y; s1.z += b.z; s1.w += b.w;
            }

            const int gb = bm * 64 + r64;
            float* po = out + (long)gb * LDR + (long)t * HH + bn * 32 + n0;
            float4 x0 = *(const float4*)po;
            float4 x1 = *(const float4*)(po + 4);
            float4 o0, o1;
            o0.x = fmaxf(x0.x + s0.x, 0.f); o0.y = fmaxf(x0.y + s0.y, 0.f);
            o0.z = fmaxf(x0.z + s0.z, 0.f); o0.w = fmaxf(x0.w + s0.w, 0.f);
            o1.x = fmaxf(x1.x + s1.x, 0.f); o1.y = fmaxf(x1.y + s1.y, 0.f);
            o1.z = fmaxf(x1.z + s1.z, 0.f); o1.w = fmaxf(x1.w + s1.w, 0.f);
            *(float4*)po = o0;
            *(float4*)(po + 4) = o1;

            uint4 hi, lo;
            split8(o0, o1, hi, lo);
            __nv_bfloat16* pa = &g_A[t & 1][gb][0];
            const int ccol = bn * 32 + n0;
            *(uint4*)(pa + ccol)        = hi;
            *(uint4*)(pa + 1024 + ccol) = lo;
        }

        if (t < TT - 1) {
            nbar++;
            grid_bar(nbar * NCTA);
        }
    }
}

// ---------------------------------------------------------------------------
extern "C" void kernel_launch(void* const* d_in, const int* in_sizes, int n_in,
                              void* d_out, int out_size)
{
    const float* x   = (const float*)d_in[0];   // [256,512,512]
    const float* Wxh = (const float*)d_in[1];   // [512,1024]
    const float* bxh = (const float*)d_in[2];   // [1024]
    const float* Whh = (const float*)d_in[3];   // [1024,1024]
    float* out = (float*)d_out;                 // [256,512,1024]

    // Prep: weight splits
    wx_convert<<<(EE * HH) / 256, 256>>>(Wxh);
    wt_convert<<<(HH * HH) / 256, 256>>>(Whh);

    // Phase 1: xh -> d_out (tensor cores, bf16 hi/lo x3)
    const int smem_p1 = 2 * 32768;
    cudaFuncSetAttribute(gemm_xh_mma,
                         cudaFuncAttributeMaxDynamicSharedMemorySize, smem_p1);
    dim3 g1(HH / 128, (BB * TT) / 128);          // (8, 1024)
    gemm_xh_mma<<<g1, 256, smem_p1>>>(x, bxh, out);

    // h0 = relu(xh_0) + bf16 split
    init_h0<<<(BB * HH) / 256, 256>>>(out);

    // Phase 2: persistent mma.sync scan (granule-triple fusion)
    const int smem_p2 = 65536 + 2 * 65536;       // A dbl 64KB + W 128KB
    cudaFuncSetAttribute(rnn_scan_mma,
                         cudaFuncAttributeMaxDynamicSharedMemorySize, smem_p2);
    rnn_scan_mma<<<NCTA, 256, smem_p2>>>(out);

    // reset grid barrier for next replay
    bar_reset<<<1, 1>>>();
}

// round 9
// speedup vs baseline: 4.0777x; 1.1278x over previous
#include <cuda_runtime.h>
#include <cuda_bf16.h>

// Problem dims (fixed by the reference)
#define BB   256      // batch
#define TT   512      // timesteps
#define EE   512      // input dim
#define HH   1024     // hidden dim
#define LDR  ((long)TT * HH)   // row stride between batches in d_out

#define NCTA 128      // persistent CTAs: 4 M-tiles (64 rows) x 32 N-tiles (32 cols)

// ---------------------------------------------------------------------------
// Scratch (device globals; no allocation allowed)
// g_Ap[buf][(tile*128 + g)*32 + lane] : hidden state in PRE-PERMUTED mma
//   fragment layout. tile = global_row>>4 (16 tiles), g = granule: hi k16
//   granules 0..63 (cols g*16..+16), lo granules 64..127. Lane L's uint4
//   holds {a0,a1,a2,a3} for the m16k16 fragment:
//     a0 = A[L>>2      ][(L&3)*2 +0/1]      a2 = A[L>>2      ][8+(L&3)*2 +0/1]
//     a1 = A[8 + (L>>2)][(L&3)*2 +0/1]      a3 = A[8 + (L>>2)][8+(L&3)*2 +0/1]
// ---------------------------------------------------------------------------
__device__ uint4 g_Ap[2][16 * 128 * 32];
__device__ __nv_bfloat16 g_Wkn[2048][HH];    // Whh: [k][n], hi rows 0..1023, lo 1024..2047
__device__ __nv_bfloat16 g_Wx[1024][HH];     // Wxh: [k][n], hi then lo

// ---------------------------------------------------------------------------
// PTX helpers (family-stable: ldmatrix + mma.sync only)
// ---------------------------------------------------------------------------
__device__ __forceinline__ unsigned smem_u32(const void* p) {
    unsigned a;
    asm("{ .reg .u64 t; cvta.to.shared.u64 t, %1; cvt.u32.u64 %0, t; }"
        : "=r"(a) : "l"(p));
    return a;
}

#define LDSM4(r, a) \
    asm volatile("ldmatrix.sync.aligned.m8n8.x4.shared.b16 {%0,%1,%2,%3}, [%4];" \
        : "=r"((r)[0]), "=r"((r)[1]), "=r"((r)[2]), "=r"((r)[3]) : "r"(a))

#define LDSM4T(r, a) \
    asm volatile("ldmatrix.sync.aligned.m8n8.x4.trans.shared.b16 {%0,%1,%2,%3}, [%4];" \
        : "=r"((r)[0]), "=r"((r)[1]), "=r"((r)[2]), "=r"((r)[3]) : "r"(a))

__device__ __forceinline__ void mma16816(float* d, const unsigned* a,
                                         unsigned b0, unsigned b1) {
    asm volatile(
        "mma.sync.aligned.m16n8k16.row.col.f32.bf16.bf16.f32 "
        "{%0,%1,%2,%3}, {%4,%5,%6,%7}, {%8,%9}, {%0,%1,%2,%3};"
        : "+f"(d[0]), "+f"(d[1]), "+f"(d[2]), "+f"(d[3])
        : "r"(a[0]), "r"(a[1]), "r"(a[2]), "r"(a[3]), "r"(b0), "r"(b1));
}

// pack 8 fp32 -> uint4 hi bf16, uint4 lo bf16
__device__ __forceinline__ void split8(float4 a, float4 b, uint4& hi, uint4& lo) {
    float s[8] = {a.x, a.y, a.z, a.w, b.x, b.y, b.z, b.w};
    unsigned h[4], l[4];
    #pragma unroll
    for (int i = 0; i < 4; i++) {
        __nv_bfloat16 h0 = __float2bfloat16(s[2 * i]);
        __nv_bfloat16 h1 = __float2bfloat16(s[2 * i + 1]);
        __nv_bfloat16 l0 = __float2bfloat16(s[2 * i] - __bfloat162float(h0));
        __nv_bfloat16 l1 = __float2bfloat16(s[2 * i + 1] - __bfloat162float(h1));
        h[i] = (unsigned)__bfloat16_as_ushort(h0)
             | ((unsigned)__bfloat16_as_ushort(h1) << 16);
        l[i] = (unsigned)__bfloat16_as_ushort(l0)
             | ((unsigned)__bfloat16_as_ushort(l1) << 16);
    }
    hi = make_uint4(h[0], h[1], h[2], h[3]);
    lo = make_uint4(l[0], l[1], l[2], l[3]);
}

// ---------------------------------------------------------------------------
// Grid-wide barrier
// ---------------------------------------------------------------------------
__device__ unsigned int g_bar = 0;
__global__ void bar_reset() { g_bar = 0; }

__device__ __forceinline__ void grid_bar(unsigned target) {
    __syncthreads();
    if (threadIdx.x == 0) {
        __threadfence();
        atomicAdd(&g_bar, 1u);
        volatile unsigned* p = &g_bar;
        while (*p < target) __nanosleep(64);
        __threadfence();
    }
    __syncthreads();
}

// ---------------------------------------------------------------------------
// Prep: weight conversions + h0
// ---------------------------------------------------------------------------
__global__ void __launch_bounds__(256)
wt_convert(const float* __restrict__ Whh)
{
    int idx = blockIdx.x * 256 + threadIdx.x;
    int k = idx >> 10, n = idx & 1023;
    float w = Whh[(long)k * HH + n];
    __nv_bfloat16 hi = __float2bfloat16(w);
    __nv_bfloat16 lo = __float2bfloat16(w - __bfloat162float(hi));
    g_Wkn[k][n] = hi;
    g_Wkn[1024 + k][n] = lo;
}

__global__ void __launch_bounds__(256)
wx_convert(const float* __restrict__ Wxh)
{
    int idx = blockIdx.x * 256 + threadIdx.x;
    int k = idx >> 10, n = idx & 1023;
    float w = Wxh[(long)k * HH + n];
    __nv_bfloat16 hi = __float2bfloat16(w);
    __nv_bfloat16 lo = __float2bfloat16(w - __bfloat162float(hi));
    g_Wx[k][n] = hi;
    g_Wx[512 + k][n] = lo;
}

// h_0 = relu(xh_0) in place + permuted bf16 hi/lo fragments into g_Ap[0]
__global__ void __launch_bounds__(256)
init_h0(float* __restrict__ out)
{
    int idx = blockIdx.x * 256 + threadIdx.x;   // 0 .. 128K-1
    int b  = idx >> 9;                          // 0..255
    int c2 = (idx & 511) * 2;                   // even col 0..1022
    float* p = out + (long)b * LDR + c2;
    float v0 = fmaxf(p[0], 0.f);
    float v1 = fmaxf(p[1], 0.f);
    p[0] = v0; p[1] = v1;

    __nv_bfloat16 h0 = __float2bfloat16(v0);
    __nv_bfloat16 h1 = __float2bfloat16(v1);
    unsigned hw = (unsigned)__bfloat16_as_ushort(h0)
                | ((unsigned)__bfloat16_as_ushort(h1) << 16);
    __nv_bfloat16 l0 = __float2bfloat16(v0 - __bfloat162float(h0));
    __nv_bfloat16 l1 = __float2bfloat16(v1 - __bfloat162float(h1));
    unsigned lw = (unsigned)__bfloat16_as_ushort(l0)
                | ((unsigned)__bfloat16_as_ushort(l1) << 16);

    int tile = b >> 4;
    int rloc = b & 15;
    int g    = c2 >> 4;
    int cb   = c2 & 15;
    int L    = ((rloc & 7) << 2) + ((cb & 7) >> 1);
    int slot = ((rloc & 8) ? 1 : 0) | ((cb & 8) ? 2 : 0);

    unsigned* dh = (unsigned*)&g_Ap[0][(tile * 128 + g) * 32 + L];
    unsigned* dl = (unsigned*)&g_Ap[0][(tile * 128 + 64 + g) * 32 + L];
    dh[slot] = hw;
    dl[slot] = lw;
}

// ---------------------------------------------------------------------------
// Phase 1 (tensor): xh = x @ Wxh + bxh  (unchanged from round 6-8)
// ---------------------------------------------------------------------------
extern __shared__ char smx[];

#define AFX(kg, m) ((unsigned)((kg) * 2048 + ((m) >> 3) * 128 + ((((m) & 7) ^ (kg)) * 16)))

__global__ void __launch_bounds__(256)
gemm_xh_mma(const float* __restrict__ x,     // [131072, 512]
            const float* __restrict__ bias,  // [1024]
            float* __restrict__ C)           // [131072, 1024]
{
    const int tid  = threadIdx.x;
    const int wid  = tid >> 5;
    const int lane = tid & 31;
    const int wr   = wid & 3;
    const int wc   = wid >> 2;
    const int bm   = blockIdx.y;
    const int bn   = blockIdx.x;

    const unsigned sb = smem_u32(smx);
    const int q   = lane >> 3;
    const int l7  = lane & 7;
    const int kgq = q >> 1;

    const int am = tid & 127;
    const int wk = tid & 31;

    float2 breg[8];
    #pragma unroll
    for (int n8 = 0; n8 < 8; n8++)
        breg[n8] = *(const float2*)&bias[bn * 128 + wc * 64 + n8 * 8 + (lane & 3) * 2];

    float acc[2][8][4];
    #pragma unroll
    for (int m = 0; m < 2; m++)
        #pragma unroll
        for (int n = 0; n < 8; n++)
            #pragma unroll
            for (int j = 0; j < 4; j++) acc[m][n][j] = 0.f;

    const float* xb = x + (long)(bm * 128) * EE;

    float4 xa[2][2];
    uint4  wvh[2], wvl[2];
    #pragma unroll
    for (int i = 0; i < 2; i++) {
        int idx = tid + i * 256;
        int kg = idx >> 7;
        const float* p = xb + (long)am * EE + kg * 8;
        xa[i][0] = *(const float4*)p;
        xa[i][1] = *(const float4*)(p + 4);
        int pp = (idx >> 5) & 15;
        wvh[i] = *(const uint4*)&g_Wx[wk][bn * 128 + pp * 8];
        wvl[i] = *(const uint4*)&g_Wx[512 + wk][bn * 128 + pp * 8];
    }
    #pragma unroll
    for (int i = 0; i < 2; i++) {
        int idx = tid + i * 256;
        int kg = idx >> 7;
        uint4 hi, lo;
        split8(xa[i][0], xa[i][1], hi, lo);
        unsigned ao = AFX(kg, am);
        *(uint4*)(smx + ao)         = hi;
        *(uint4*)(smx + 8192 + ao)  = lo;
        int pp = (idx >> 5) & 15;
        unsigned wo = 16384u + (unsigned)pp * 512u + (unsigned)wk * 16u;
        *(uint4*)(smx + wo)         = wvh[i];
        *(uint4*)(smx + 8192 + wo)  = wvl[i];
    }
    __syncthreads();

    unsigned buf = 0;
    for (int kc = 0; kc < 16; kc++) {
        const bool more = (kc + 1 < 16);
        if (more) {
            const int k0 = (kc + 1) * 32;
            #pragma unroll
            for (int i = 0; i < 2; i++) {
                int idx = tid + i * 256;
                int kg = idx >> 7;
                const float* p = xb + (long)am * EE + k0 + kg * 8;
                xa[i][0] = *(const float4*)p;
                xa[i][1] = *(const float4*)(p + 4);
                int pp = (idx >> 5) & 15;
                wvh[i] = *(const uint4*)&g_Wx[k0 + wk][bn * 128 + pp * 8];
                wvl[i] = *(const uint4*)&g_Wx[512 + k0 + wk][bn * 128 + pp * 8];
            }
        }

        const unsigned B0 = sb + buf * 32768u;
        #pragma unroll
        for (int s16 = 0; s16 < 2; s16++) {
            const int kg = s16 * 2 + kgq;
            const unsigned aoff = (unsigned)kg * 2048u + (unsigned)((l7 ^ kg) * 16);
            unsigned ahi[2][4], alo[2][4];
            LDSM4(ahi[0], B0 + aoff + (unsigned)(wr * 4 + 0 + (q & 1)) * 128u);
            LDSM4(ahi[1], B0 + aoff + (unsigned)(wr * 4 + 2 + (q & 1)) * 128u);
            LDSM4(alo[0], B0 + 8192u + aoff + (unsigned)(wr * 4 + 0 + (q & 1)) * 128u);
            LDSM4(alo[1], B0 + 8192u + aoff + (unsigned)(wr * 4 + 2 + (q & 1)) * 128u);

            const unsigned wrow = (unsigned)(s16 * 16 + (q & 1) * 8 + l7) * 16u;
            #pragma unroll
            for (int pp = 0; pp < 4; pp++) {
                unsigned wh[4], wl[4];
                unsigned wbase = B0 + 16384u
                               + (unsigned)(wc * 8 + pp * 2 + kgq) * 512u + wrow;
                LDSM4T(wh, wbase);
                LDSM4T(wl, wbase + 8192u);
                const int n0 = pp * 2, n1 = pp * 2 + 1;
                mma16816(acc[0][n0], ahi[0], wh[0], wh[1]);
                mma16816(acc[0][n1], ahi[0], wh[2], wh[3]);
                mma16816(acc[1][n0], ahi[1], wh[0], wh[1]);
                mma16816(acc[1][n1], ahi[1], wh[2], wh[3]);
                mma16816(acc[0][n0], alo[0], wh[0], wh[1]);
                mma16816(acc[0][n1], alo[0], wh[2], wh[3]);
                mma16816(acc[1][n0], alo[1], wh[0], wh[1]);
                mma16816(acc[1][n1], alo[1], wh[2], wh[3]);
                mma16816(acc[0][n0], ahi[0], wl[0], wl[1]);
                mma16816(acc[0][n1], ahi[0], wl[2], wl[3]);
                mma16816(acc[1][n0], ahi[1], wl[0], wl[1]);
                mma16816(acc[1][n1], ahi[1], wl[2], wl[3]);
            }
        }

        if (more) {
            const unsigned nb = (buf ^ 1u) * 32768u;
            #pragma unroll
            for (int i = 0; i < 2; i++) {
                int idx = tid + i * 256;
                int kg = idx >> 7;
                uint4 hi, lo;
                split8(xa[i][0], xa[i][1], hi, lo);
                unsigned ao = nb + AFX(kg, am);
                *(uint4*)(smx + ao)        = hi;
                *(uint4*)(smx + 8192 + ao) = lo;
                int pp = (idx >> 5) & 15;
                unsigned wo = nb + 16384u + (unsigned)pp * 512u + (unsigned)wk * 16u;
                *(uint4*)(smx + wo)        = wvh[i];
                *(uint4*)(smx + 8192 + wo) = wvl[i];
            }
            __syncthreads();
            buf ^= 1u;
        }
    }

    #pragma unroll
    for (int mm = 0; mm < 2; mm++) {
        #pragma unroll
        for (int half = 0; half < 2; half++) {
            long row = (long)bm * 128 + wr * 32 + mm * 16 + (lane >> 2) + half * 8;
            float* pr = C + row * HH + bn * 128 + wc * 64 + (lane & 3) * 2;
            #pragma unroll
            for (int n8 = 0; n8 < 8; n8++) {
                float2 o;
                o.x = acc[mm][n8][half * 2 + 0] + breg[n8].x;
                o.y = acc[mm][n8][half * 2 + 1] + breg[n8].y;
                *(float2*)(pr + n8 * 8) = o;
            }
        }
    }
}

// ---------------------------------------------------------------------------
// Phase 2: persistent mma.sync scan — fragment-resident state.
// A fragments are loaded straight from g_Ap (L2) with coalesced LDG.128 —
// NO smem staging, NO per-chunk syncthreads. W resident in smem (once):
// hi @0, lo @64KB; 4 panels [1024k][8n]. Warp kq owns granules gk = i*8+kq
// and computes the full triple {AhiWhi, AhiWlo, AloWhi} at m64 x n32 into a
// fp32 partial; k-reduction via smem @128KB + fused epilogue that writes
// fp32 out and the NEXT step's permuted fragments.
// ---------------------------------------------------------------------------
__global__ void __launch_bounds__(256, 1)
rnn_scan_mma(float* __restrict__ out)
{
    const int tid  = threadIdx.x;
    const int kq   = tid >> 5;          // warp = k16-granule owner 0..7
    const int lane = tid & 31;
    const int bm   = blockIdx.x >> 5;   // 0..3
    const int bn   = blockIdx.x & 31;   // 0..31

    const unsigned sb = smem_u32(smx);

    // ---- stage W slice into SMEM panels (once): hi @0, lo @65536 ----
    for (int i = 0; i < 32; i++) {
        int kk = i * 64 + (tid >> 2);      // 0..2047 packed k
        int p  = tid & 3;                  // n8 panel
        uint4 v = *(const uint4*)&g_Wkn[kk][bn * 32 + p * 8];
        unsigned off = (unsigned)(kk >> 10) * 65536u
                     + (unsigned)p * 16384u + (unsigned)(kk & 1023) * 16u;
        *(uint4*)(smx + off) = v;
    }
    __syncthreads();

    // W ldmatrix lane addressing
    const int q   = lane >> 3;
    const int l7  = lane & 7;
    const int kgq = q >> 1;
    const unsigned wrowsel = (unsigned)((q & 1) * 8 + l7) * 16u;
    const unsigned whiBase = sb + (unsigned)kgq * 16384u + wrowsel;
    const unsigned wloBase = whiBase + 65536u;

    // partial-store mapping
    const int eg = lane >> 2;           // 0..7
    const int ei = lane & 3;            // 0..3
    // reduction / epilogue mapping
    const int r64 = tid >> 2;           // 0..63
    const int n0  = (tid & 3) * 8;      // 0,8,16,24

    const int bm4 = bm * 4;
    unsigned nbar = 0;

    for (int t = 1; t < TT; t++) {
        const uint4* Ab = &g_Ap[(t + 1) & 1][0];

        float d[4][4][4];                // [mi][n8][frag]
        #pragma unroll
        for (int mi = 0; mi < 4; mi++)
            #pragma unroll
            for (int nt = 0; nt < 4; nt++)
                #pragma unroll
                for (int j = 0; j < 4; j++) d[mi][nt][j] = 0.f;

        uint4 cur[8], nxt[8];

        // prefetch granule-set 0 (gk = kq): hi + lo frags for 4 m-tiles
        #pragma unroll
        for (int mi = 0; mi < 4; mi++) {
            cur[mi * 2 + 0] = Ab[((bm4 + mi) * 128 + kq) * 32 + lane];
            cur[mi * 2 + 1] = Ab[((bm4 + mi) * 128 + 64 + kq) * 32 + lane];
        }

        #pragma unroll
        for (int i = 0; i < 8; i++) {
            if (i < 7) {
                const int gk1 = (i + 1) * 8 + kq;
                #pragma unroll
                for (int mi = 0; mi < 4; mi++) {
                    nxt[mi * 2 + 0] = Ab[((bm4 + mi) * 128 + gk1) * 32 + lane];
                    nxt[mi * 2 + 1] = Ab[((bm4 + mi) * 128 + 64 + gk1) * 32 + lane];
                }
            }

            const int gk = i * 8 + kq;
            const unsigned wko = (unsigned)gk * 256u;
            unsigned wh1[4], wh2[4], wl1[4], wl2[4];
            LDSM4T(wh1, whiBase + wko);
            LDSM4T(wh2, whiBase + 32768u + wko);
            LDSM4T(wl1, wloBase + wko);
            LDSM4T(wl2, wloBase + 32768u + wko);

            #pragma unroll
            for (int mi = 0; mi < 4; mi++) {
                const unsigned* ahi = (const unsigned*)&cur[mi * 2 + 0];
                const unsigned* alo = (const unsigned*)&cur[mi * 2 + 1];
                mma16816(d[mi][0], ahi, wh1[0], wh1[1]);
                mma16816(d[mi][1], ahi, wh1[2], wh1[3]);
                mma16816(d[mi][2], ahi, wh2[0], wh2[1]);
                mma16816(d[mi][3], ahi, wh2[2], wh2[3]);
                mma16816(d[mi][0], ahi, wl1[0], wl1[1]);
                mma16816(d[mi][1], ahi, wl1[2], wl1[3]);
                mma16816(d[mi][2], ahi, wl2[0], wl2[1]);
                mma16816(d[mi][3], ahi, wl2[2], wl2[3]);
                mma16816(d[mi][0], alo, wh1[0], wh1[1]);
                mma16816(d[mi][1], alo, wh1[2], wh1[3]);
                mma16816(d[mi][2], alo, wh2[0], wh2[1]);
                mma16816(d[mi][3], alo, wh2[2], wh2[3]);
            }

            if (i < 7) {
                #pragma unroll
                for (int j = 0; j < 8; j++) cur[j] = nxt[j];
            }
        }

        // ---- store 64x32 fp32 partial (XOR-16 swizzle on rows) @128KB ----
        {
            const unsigned pb = 131072u + (unsigned)(kq * 8192);
            #pragma unroll
            for (int mi = 0; mi < 4; mi++) {
                #pragma unroll
                for (int half = 0; half < 2; half++) {
                    const int r = mi * 16 + eg + half * 8;   // 0..63
                    const unsigned xr = (unsigned)((r & 7) * 16);
                    #pragma unroll
                    for (int nt = 0; nt < 4; nt++) {
                        float2 pv;
                        pv.x = d[mi][nt][half * 2 + 0];
                        pv.y = d[mi][nt][half * 2 + 1];
                        unsigned cb = (unsigned)(nt * 32 + ei * 8) ^ xr;
                        *(float2*)(smx + pb + (unsigned)r * 128u + cb) = pv;
                    }
                }
            }
        }
        __syncthreads();

        // ---- reduce 8 partials + fused epilogue ----
        {
            const unsigned xr = (unsigned)((r64 & 7) * 16);
            const unsigned c0 = ((unsigned)(n0 * 4)) ^ xr;
            const unsigned c1 = ((unsigned)(n0 * 4 + 16)) ^ xr;
            float4 s0 = {0.f, 0.f, 0.f, 0.f}, s1 = {0.f, 0.f, 0.f, 0.f};
            #pragma unroll
            for (int p = 0; p < 8; p++) {
                const char* pp = smx + 131072u + (unsigned)(p * 8192)
                               + (unsigned)r64 * 128u;
                float4 a = *(const float4*)(pp + c0);
                float4 b = *(const float4*)(pp + c1);
                s0.x += a.x; s0.y += a.y; s0.z += a.z; s0.w += a.w;
                s1.x += b.x; s1.y += b.y; s1.z += b.z; s1.w += b.w;
            }

            const int gb = bm * 64 + r64;
            float* po = out + (long)gb * LDR + (long)t * HH + bn * 32 + n0;
            float4 x0 = *(const float4*)po;
            float4 x1 = *(const float4*)(po + 4);
            float4 o0, o1;
            o0.x = fmaxf(x0.x + s0.x, 0.f); o0.y = fmaxf(x0.y + s0.y, 0.f);
            o0.z = fmaxf(x0.z + s0.z, 0.f); o0.w = fmaxf(x0.w + s0.w, 0.f);
            o1.x = fmaxf(x1.x + s1.x, 0.f); o1.y = fmaxf(x1.y + s1.y, 0.f);
            o1.z = fmaxf(x1.z + s1.z, 0.f); o1.w = fmaxf(x1.w + s1.w, 0.f);
            *(float4*)po = o0;
            *(float4*)(po + 4) = o1;

            // write next-step permuted fragments (hi + lo words)
            float sv[8] = {o0.x, o0.y, o0.z, o0.w, o1.x, o1.y, o1.z, o1.w};
            const int tile = gb >> 4;
            const int rloc = gb & 15;
            const int Cb   = bn * 32 + n0;
            const int g    = Cb >> 4;
            const int slot = ((rloc & 8) ? 1 : 0) | ((Cb & 8) ? 2 : 0);
            unsigned* dh = (unsigned*)&g_Ap[t & 1][(tile * 128 + g) * 32];
            unsigned* dl = (unsigned*)&g_Ap[t & 1][(tile * 128 + 64 + g) * 32];
            #pragma unroll
            for (int j = 0; j < 4; j++) {
                float v0 = sv[2 * j], v1 = sv[2 * j + 1];
                __nv_bfloat16 h0 = __float2bfloat16(v0);
                __nv_bfloat16 h1 = __float2bfloat16(v1);
                unsigned hw = (unsigned)__bfloat16_as_ushort(h0)
                            | ((unsigned)__bfloat16_as_ushort(h1) << 16);
                __nv_bfloat16 l0 = __float2bfloat16(v0 - __bfloat162float(h0));
                __nv_bfloat16 l1 = __float2bfloat16(v1 - __bfloat162float(h1));
                unsigned lw = (unsigned)__bfloat16_as_ushort(l0)
                            | ((unsigned)__bfloat16_as_ushort(l1) << 16);
                const int L = ((rloc & 7) << 2) + j;
                dh[L * 4 + slot] = hw;
                dl[L * 4 + slot] = lw;
            }
        }

        if (t < TT - 1) {
            nbar++;
            grid_bar(nbar * NCTA);
        }
    }
}

// ---------------------------------------------------------------------------
extern "C" void kernel_launch(void* const* d_in, const int* in_sizes, int n_in,
                              void* d_out, int out_size)
{
    const float* x   = (const float*)d_in[0];   // [256,512,512]
    const float* Wxh = (const float*)d_in[1];   // [512,1024]
    const float* bxh = (const float*)d_in[2];   // [1024]
    const float* Whh = (const float*)d_in[3];   // [1024,1024]
    float* out = (float*)d_out;                 // [256,512,1024]

    // Prep: weight splits
    wx_convert<<<(EE * HH) / 256, 256>>>(Wxh);
    wt_convert<<<(HH * HH) / 256, 256>>>(Whh);

    // Phase 1: xh -> d_out (tensor cores, bf16 hi/lo x3)
    const int smem_p1 = 2 * 32768;
    cudaFuncSetAttribute(gemm_xh_mma,
                         cudaFuncAttributeMaxDynamicSharedMemorySize, smem_p1);
    dim3 g1(HH / 128, (BB * TT) / 128);          // (8, 1024)
    gemm_xh_mma<<<g1, 256, smem_p1>>>(x, bxh, out);

    // h0 = relu(xh_0) + permuted fragment split
    init_h0<<<(BB * HH / 2) / 256, 256>>>(out);

    // Phase 2: persistent mma.sync scan (fragment-resident state)
    const int smem_p2 = 131072 + 65536;          // W 128KB + partials 64KB
    cudaFuncSetAttribute(rnn_scan_mma,
                         cudaFuncAttributeMaxDynamicSharedMemorySize, smem_p2);
    rnn_scan_mma<<<NCTA, 256, smem_p2>>>(out);

    // reset grid barrier for next replay
    bar_reset<<<1, 1>>>();
}

// round 10
// speedup vs baseline: 4.2456x; 1.0412x over previous
#include <cuda_runtime.h>
#include <cuda_bf16.h>

// Problem dims (fixed by the reference)
#define BB   256      // batch
#define TT   512      // timesteps
#define EE   512      // input dim
#define HH   1024     // hidden dim
#define LDR  ((long)TT * HH)   // row stride between batches in d_out

#define NCTA 128      // persistent CTAs: 4 M-tiles (64 rows) x 32 N-tiles (32 cols)

// ---------------------------------------------------------------------------
// Scratch (device globals; no allocation allowed)
// g_Ap[buf][(tile*128 + g)*32 + lane] : hidden state in PRE-PERMUTED mma
//   fragment layout (see round 9 comment).
// ---------------------------------------------------------------------------
__device__ uint4 g_Ap[2][16 * 128 * 32];
__device__ __nv_bfloat16 g_Wkn[2048][HH];    // Whh: [k][n], hi rows 0..1023, lo 1024..2047
__device__ __nv_bfloat16 g_Wx[1024][HH];     // Wxh: [k][n], hi then lo

// ---------------------------------------------------------------------------
// PTX helpers (family-stable: ldmatrix + mma.sync only)
// ---------------------------------------------------------------------------
__device__ __forceinline__ unsigned smem_u32(const void* p) {
    unsigned a;
    asm("{ .reg .u64 t; cvta.to.shared.u64 t, %1; cvt.u32.u64 %0, t; }"
        : "=r"(a) : "l"(p));
    return a;
}

#define LDSM4(r, a) \
    asm volatile("ldmatrix.sync.aligned.m8n8.x4.shared.b16 {%0,%1,%2,%3}, [%4];" \
        : "=r"((r)[0]), "=r"((r)[1]), "=r"((r)[2]), "=r"((r)[3]) : "r"(a))

#define LDSM4T(r, a) \
    asm volatile("ldmatrix.sync.aligned.m8n8.x4.trans.shared.b16 {%0,%1,%2,%3}, [%4];" \
        : "=r"((r)[0]), "=r"((r)[1]), "=r"((r)[2]), "=r"((r)[3]) : "r"(a))

__device__ __forceinline__ void mma16816(float* d, const unsigned* a,
                                         unsigned b0, unsigned b1) {
    asm volatile(
        "mma.sync.aligned.m16n8k16.row.col.f32.bf16.bf16.f32 "
        "{%0,%1,%2,%3}, {%4,%5,%6,%7}, {%8,%9}, {%0,%1,%2,%3};"
        : "+f"(d[0]), "+f"(d[1]), "+f"(d[2]), "+f"(d[3])
        : "r"(a[0]), "r"(a[1]), "r"(a[2]), "r"(a[3]), "r"(b0), "r"(b1));
}

// pack 8 fp32 -> uint4 hi bf16, uint4 lo bf16
__device__ __forceinline__ void split8(float4 a, float4 b, uint4& hi, uint4& lo) {
    float s[8] = {a.x, a.y, a.z, a.w, b.x, b.y, b.z, b.w};
    unsigned h[4], l[4];
    #pragma unroll
    for (int i = 0; i < 4; i++) {
        __nv_bfloat16 h0 = __float2bfloat16(s[2 * i]);
        __nv_bfloat16 h1 = __float2bfloat16(s[2 * i + 1]);
        __nv_bfloat16 l0 = __float2bfloat16(s[2 * i] - __bfloat162float(h0));
        __nv_bfloat16 l1 = __float2bfloat16(s[2 * i + 1] - __bfloat162float(h1));
        h[i] = (unsigned)__bfloat16_as_ushort(h0)
             | ((unsigned)__bfloat16_as_ushort(h1) << 16);
        l[i] = (unsigned)__bfloat16_as_ushort(l0)
             | ((unsigned)__bfloat16_as_ushort(l1) << 16);
    }
    hi = make_uint4(h[0], h[1], h[2], h[3]);
    lo = make_uint4(l[0], l[1], l[2], l[3]);
}

// ---------------------------------------------------------------------------
// Per-bm-group barriers (4 independent groups of 32 CTAs), 128B apart
// ---------------------------------------------------------------------------
__device__ unsigned int g_bar4[4 * 32];
__global__ void bar_reset() {
    if (threadIdx.x < 128) g_bar4[threadIdx.x] = 0;
}

// ---------------------------------------------------------------------------
// Prep: weight conversions + h0
// ---------------------------------------------------------------------------
__global__ void __launch_bounds__(256)
wt_convert(const float* __restrict__ Whh)
{
    int idx = blockIdx.x * 256 + threadIdx.x;
    int k = idx >> 10, n = idx & 1023;
    float w = Whh[(long)k * HH + n];
    __nv_bfloat16 hi = __float2bfloat16(w);
    __nv_bfloat16 lo = __float2bfloat16(w - __bfloat162float(hi));
    g_Wkn[k][n] = hi;
    g_Wkn[1024 + k][n] = lo;
}

__global__ void __launch_bounds__(256)
wx_convert(const float* __restrict__ Wxh)
{
    int idx = blockIdx.x * 256 + threadIdx.x;
    int k = idx >> 10, n = idx & 1023;
    float w = Wxh[(long)k * HH + n];
    __nv_bfloat16 hi = __float2bfloat16(w);
    __nv_bfloat16 lo = __float2bfloat16(w - __bfloat162float(hi));
    g_Wx[k][n] = hi;
    g_Wx[512 + k][n] = lo;
}

// h_0 = relu(xh_0) in place + permuted bf16 hi/lo fragments into g_Ap[0]
__global__ void __launch_bounds__(256)
init_h0(float* __restrict__ out)
{
    int idx = blockIdx.x * 256 + threadIdx.x;   // 0 .. 128K-1
    int b  = idx >> 9;                          // 0..255
    int c2 = (idx & 511) * 2;                   // even col 0..1022
    float* p = out + (long)b * LDR + c2;
    float v0 = fmaxf(p[0], 0.f);
    float v1 = fmaxf(p[1], 0.f);
    p[0] = v0; p[1] = v1;

    __nv_bfloat16 h0 = __float2bfloat16(v0);
    __nv_bfloat16 h1 = __float2bfloat16(v1);
    unsigned hw = (unsigned)__bfloat16_as_ushort(h0)
                | ((unsigned)__bfloat16_as_ushort(h1) << 16);
    __nv_bfloat16 l0 = __float2bfloat16(v0 - __bfloat162float(h0));
    __nv_bfloat16 l1 = __float2bfloat16(v1 - __bfloat162float(h1));
    unsigned lw = (unsigned)__bfloat16_as_ushort(l0)
                | ((unsigned)__bfloat16_as_ushort(l1) << 16);

    int tile = b >> 4;
    int rloc = b & 15;
    int g    = c2 >> 4;
    int cb   = c2 & 15;
    int L    = ((rloc & 7) << 2) + ((cb & 7) >> 1);
    int slot = ((rloc & 8) ? 1 : 0) | ((cb & 8) ? 2 : 0);

    unsigned* dh = (unsigned*)&g_Ap[0][(tile * 128 + g) * 32 + L];
    unsigned* dl = (unsigned*)&g_Ap[0][(tile * 128 + 64 + g) * 32 + L];
    dh[slot] = hw;
    dl[slot] = lw;
}

// ---------------------------------------------------------------------------
// Phase 1 (tensor): xh = x @ Wxh + bxh  (unchanged from round 6-9)
// ---------------------------------------------------------------------------
extern __shared__ char smx[];

#define AFX(kg, m) ((unsigned)((kg) * 2048 + ((m) >> 3) * 128 + ((((m) & 7) ^ (kg)) * 16)))

__global__ void __launch_bounds__(256)
gemm_xh_mma(const float* __restrict__ x,     // [131072, 512]
            const float* __restrict__ bias,  // [1024]
            float* __restrict__ C)           // [131072, 1024]
{
    const int tid  = threadIdx.x;
    const int wid  = tid >> 5;
    const int lane = tid & 31;
    const int wr   = wid & 3;
    const int wc   = wid >> 2;
    const int bm   = blockIdx.y;
    const int bn   = blockIdx.x;

    const unsigned sb = smem_u32(smx);
    const int q   = lane >> 3;
    const int l7  = lane & 7;
    const int kgq = q >> 1;

    const int am = tid & 127;
    const int wk = tid & 31;

    float2 breg[8];
    #pragma unroll
    for (int n8 = 0; n8 < 8; n8++)
        breg[n8] = *(const float2*)&bias[bn * 128 + wc * 64 + n8 * 8 + (lane & 3) * 2];

    float acc[2][8][4];
    #pragma unroll
    for (int m = 0; m < 2; m++)
        #pragma unroll
        for (int n = 0; n < 8; n++)
            #pragma unroll
            for (int j = 0; j < 4; j++) acc[m][n][j] = 0.f;

    const float* xb = x + (long)(bm * 128) * EE;

    float4 xa[2][2];
    uint4  wvh[2], wvl[2];
    #pragma unroll
    for (int i = 0; i < 2; i++) {
        int idx = tid + i * 256;
        int kg = idx >> 7;
        const float* p = xb + (long)am * EE + kg * 8;
        xa[i][0] = *(const float4*)p;
        xa[i][1] = *(const float4*)(p + 4);
        int pp = (idx >> 5) & 15;
        wvh[i] = *(const uint4*)&g_Wx[wk][bn * 128 + pp * 8];
        wvl[i] = *(const uint4*)&g_Wx[512 + wk][bn * 128 + pp * 8];
    }
    #pragma unroll
    for (int i = 0; i < 2; i++) {
        int idx = tid + i * 256;
        int kg = idx >> 7;
        uint4 hi, lo;
        split8(xa[i][0], xa[i][1], hi, lo);
        unsigned ao = AFX(kg, am);
        *(uint4*)(smx + ao)         = hi;
        *(uint4*)(smx + 8192 + ao)  = lo;
        int pp = (idx >> 5) & 15;
        unsigned wo = 16384u + (unsigned)pp * 512u + (unsigned)wk * 16u;
        *(uint4*)(smx + wo)         = wvh[i];
        *(uint4*)(smx + 8192 + wo)  = wvl[i];
    }
    __syncthreads();

    unsigned buf = 0;
    for (int kc = 0; kc < 16; kc++) {
        const bool more = (kc + 1 < 16);
        if (more) {
            const int k0 = (kc + 1) * 32;
            #pragma unroll
            for (int i = 0; i < 2; i++) {
                int idx = tid + i * 256;
                int kg = idx >> 7;
                const float* p = xb + (long)am * EE + k0 + kg * 8;
                xa[i][0] = *(const float4*)p;
                xa[i][1] = *(const float4*)(p + 4);
                int pp = (idx >> 5) & 15;
                wvh[i] = *(const uint4*)&g_Wx[k0 + wk][bn * 128 + pp * 8];
                wvl[i] = *(const uint4*)&g_Wx[512 + k0 + wk][bn * 128 + pp * 8];
            }
        }

        const unsigned B0 = sb + buf * 32768u;
        #pragma unroll
        for (int s16 = 0; s16 < 2; s16++) {
            const int kg = s16 * 2 + kgq;
            const unsigned aoff = (unsigned)kg * 2048u + (unsigned)((l7 ^ kg) * 16);
            unsigned ahi[2][4], alo[2][4];
            LDSM4(ahi[0], B0 + aoff + (unsigned)(wr * 4 + 0 + (q & 1)) * 128u);
            LDSM4(ahi[1], B0 + aoff + (unsigned)(wr * 4 + 2 + (q & 1)) * 128u);
            LDSM4(alo[0], B0 + 8192u + aoff + (unsigned)(wr * 4 + 0 + (q & 1)) * 128u);
            LDSM4(alo[1], B0 + 8192u + aoff + (unsigned)(wr * 4 + 2 + (q & 1)) * 128u);

            const unsigned wrow = (unsigned)(s16 * 16 + (q & 1) * 8 + l7) * 16u;
            #pragma unroll
            for (int pp = 0; pp < 4; pp++) {
                unsigned wh[4], wl[4];
                unsigned wbase = B0 + 16384u
                               + (unsigned)(wc * 8 + pp * 2 + kgq) * 512u + wrow;
                LDSM4T(wh, wbase);
                LDSM4T(wl, wbase + 8192u);
                const int n0 = pp * 2, n1 = pp * 2 + 1;
                mma16816(acc[0][n0], ahi[0], wh[0], wh[1]);
                mma16816(acc[0][n1], ahi[0], wh[2], wh[3]);
                mma16816(acc[1][n0], ahi[1], wh[0], wh[1]);
                mma16816(acc[1][n1], ahi[1], wh[2], wh[3]);
                mma16816(acc[0][n0], alo[0], wh[0], wh[1]);
                mma16816(acc[0][n1], alo[0], wh[2], wh[3]);
                mma16816(acc[1][n0], alo[1], wh[0], wh[1]);
                mma16816(acc[1][n1], alo[1], wh[2], wh[3]);
                mma16816(acc[0][n0], ahi[0], wl[0], wl[1]);
                mma16816(acc[0][n1], ahi[0], wl[2], wl[3]);
                mma16816(acc[1][n0], ahi[1], wl[0], wl[1]);
                mma16816(acc[1][n1], ahi[1], wl[2], wl[3]);
            }
        }

        if (more) {
            const unsigned nb = (buf ^ 1u) * 32768u;
            #pragma unroll
            for (int i = 0; i < 2; i++) {
                int idx = tid + i * 256;
                int kg = idx >> 7;
                uint4 hi, lo;
                split8(xa[i][0], xa[i][1], hi, lo);
                unsigned ao = nb + AFX(kg, am);
                *(uint4*)(smx + ao)        = hi;
                *(uint4*)(smx + 8192 + ao) = lo;
                int pp = (idx >> 5) & 15;
                unsigned wo = nb + 16384u + (unsigned)pp * 512u + (unsigned)wk * 16u;
                *(uint4*)(smx + wo)        = wvh[i];
                *(uint4*)(smx + 8192 + wo) = wvl[i];
            }
            __syncthreads();
            buf ^= 1u;
        }
    }

    #pragma unroll
    for (int mm = 0; mm < 2; mm++) {
        #pragma unroll
        for (int half = 0; half < 2; half++) {
            long row = (long)bm * 128 + wr * 32 + mm * 16 + (lane >> 2) + half * 8;
            float* pr = C + row * HH + bn * 128 + wc * 64 + (lane & 3) * 2;
            #pragma unroll
            for (int n8 = 0; n8 < 8; n8++) {
                float2 o;
                o.x = acc[mm][n8][half * 2 + 0] + breg[n8].x;
                o.y = acc[mm][n8][half * 2 + 1] + breg[n8].y;
                *(float2*)(pr + n8 * 8) = o;
            }
        }
    }
}

// ---------------------------------------------------------------------------
// Phase 2: persistent mma.sync scan — fragment-resident state, grouped sync.
// Same math as round 9. New: (1) per-bm barrier groups (4 x 32 CTAs, fully
// independent scans); (2) xh slice prefetched at step start (hides DRAM);
// (3) barrier arrive immediately after fragment writes, fp32 out store
// overlapped with other CTAs' arrival.
// ---------------------------------------------------------------------------
__global__ void __launch_bounds__(256, 1)
rnn_scan_mma(float* __restrict__ out)
{
    const int tid  = threadIdx.x;
    const int kq   = tid >> 5;          // warp = k16-granule owner 0..7
    const int lane = tid & 31;
    const int bm   = blockIdx.x >> 5;   // 0..3
    const int bn   = blockIdx.x & 31;   // 0..31

    const unsigned sb = smem_u32(smx);

    // ---- stage W slice into SMEM panels (once): hi @0, lo @65536 ----
    for (int i = 0; i < 32; i++) {
        int kk = i * 64 + (tid >> 2);      // 0..2047 packed k
        int p  = tid & 3;                  // n8 panel
        uint4 v = *(const uint4*)&g_Wkn[kk][bn * 32 + p * 8];
        unsigned off = (unsigned)(kk >> 10) * 65536u
                     + (unsigned)p * 16384u + (unsigned)(kk & 1023) * 16u;
        *(uint4*)(smx + off) = v;
    }
    __syncthreads();

    // W ldmatrix lane addressing
    const int q   = lane >> 3;
    const int l7  = lane & 7;
    const int kgq = q >> 1;
    const unsigned wrowsel = (unsigned)((q & 1) * 8 + l7) * 16u;
    const unsigned whiBase = sb + (unsigned)kgq * 16384u + wrowsel;
    const unsigned wloBase = whiBase + 65536u;

    // partial-store mapping
    const int eg = lane >> 2;           // 0..7
    const int ei = lane & 3;            // 0..3
    // reduction / epilogue mapping
    const int r64 = tid >> 2;           // 0..63
    const int n0  = (tid & 3) * 8;      // 0,8,16,24

    const int bm4 = bm * 4;
    unsigned* const barp = &g_bar4[bm * 32];
    unsigned nbar = 0;

    // epilogue constants
    const int gb   = bm * 64 + r64;
    const int tileE = gb >> 4;
    const int rloc  = gb & 15;
    const int Cb    = bn * 32 + n0;
    const int gE    = Cb >> 4;
    const int slot  = ((rloc & 8) ? 1 : 0) | ((Cb & 8) ? 2 : 0);

    for (int t = 1; t < TT; t++) {
        const uint4* Ab = &g_Ap[(t + 1) & 1][0];

        // prefetch the xh slice for this step (h-independent; hides DRAM)
        float* po = out + (long)gb * LDR + (long)t * HH + Cb;
        float4 x0p = *(const float4*)po;
        float4 x1p = *(const float4*)(po + 4);

        float d[4][4][4];                // [mi][n8][frag]
        #pragma unroll
        for (int mi = 0; mi < 4; mi++)
            #pragma unroll
            for (int nt = 0; nt < 4; nt++)
                #pragma unroll
                for (int j = 0; j < 4; j++) d[mi][nt][j] = 0.f;

        uint4 cur[8], nxt[8];

        // prefetch granule-set 0 (gk = kq): hi + lo frags for 4 m-tiles
        #pragma unroll
        for (int mi = 0; mi < 4; mi++) {
            cur[mi * 2 + 0] = Ab[((bm4 + mi) * 128 + kq) * 32 + lane];
            cur[mi * 2 + 1] = Ab[((bm4 + mi) * 128 + 64 + kq) * 32 + lane];
        }

        #pragma unroll
        for (int i = 0; i < 8; i++) {
            if (i < 7) {
                const int gk1 = (i + 1) * 8 + kq;
                #pragma unroll
                for (int mi = 0; mi < 4; mi++) {
                    nxt[mi * 2 + 0] = Ab[((bm4 + mi) * 128 + gk1) * 32 + lane];
                    nxt[mi * 2 + 1] = Ab[((bm4 + mi) * 128 + 64 + gk1) * 32 + lane];
                }
            }

            const int gk = i * 8 + kq;
            const unsigned wko = (unsigned)gk * 256u;
            unsigned wh1[4], wh2[4], wl1[4], wl2[4];
            LDSM4T(wh1, whiBase + wko);
            LDSM4T(wh2, whiBase + 32768u + wko);
            LDSM4T(wl1, wloBase + wko);
            LDSM4T(wl2, wloBase + 32768u + wko);

            #pragma unroll
            for (int mi = 0; mi < 4; mi++) {
                const unsigned* ahi = (const unsigned*)&cur[mi * 2 + 0];
                const unsigned* alo = (const unsigned*)&cur[mi * 2 + 1];
                mma16816(d[mi][0], ahi, wh1[0], wh1[1]);
                mma16816(d[mi][1], ahi, wh1[2], wh1[3]);
                mma16816(d[mi][2], ahi, wh2[0], wh2[1]);
                mma16816(d[mi][3], ahi, wh2[2], wh2[3]);
                mma16816(d[mi][0], ahi, wl1[0], wl1[1]);
                mma16816(d[mi][1], ahi, wl1[2], wl1[3]);
                mma16816(d[mi][2], ahi, wl2[0], wl2[1]);
                mma16816(d[mi][3], ahi, wl2[2], wl2[3]);
                mma16816(d[mi][0], alo, wh1[0], wh1[1]);
                mma16816(d[mi][1], alo, wh1[2], wh1[3]);
                mma16816(d[mi][2], alo, wh2[0], wh2[1]);
                mma16816(d[mi][3], alo, wh2[2], wh2[3]);
            }

            if (i < 7) {
                #pragma unroll
                for (int j = 0; j < 8; j++) cur[j] = nxt[j];
            }
        }

        // ---- store 64x32 fp32 partial (XOR-16 swizzle on rows) @128KB ----
        {
            const unsigned pb = 131072u + (unsigned)(kq * 8192);
            #pragma unroll
            for (int mi = 0; mi < 4; mi++) {
                #pragma unroll
                for (int half = 0; half < 2; half++) {
                    const int r = mi * 16 + eg + half * 8;   // 0..63
                    const unsigned xr = (unsigned)((r & 7) * 16);
                    #pragma unroll
                    for (int nt = 0; nt < 4; nt++) {
                        float2 pv;
                        pv.x = d[mi][nt][half * 2 + 0];
                        pv.y = d[mi][nt][half * 2 + 1];
                        unsigned cb = (unsigned)(nt * 32 + ei * 8) ^ xr;
                        *(float2*)(smx + pb + (unsigned)r * 128u + cb) = pv;
                    }
                }
            }
        }
        __syncthreads();

        // ---- reduce 8 partials + fused epilogue ----
        float4 o0, o1;
        {
            const unsigned xr = (unsigned)((r64 & 7) * 16);
            const unsigned c0 = ((unsigned)(n0 * 4)) ^ xr;
            const unsigned c1 = ((unsigned)(n0 * 4 + 16)) ^ xr;
            float4 s0 = {0.f, 0.f, 0.f, 0.f}, s1 = {0.f, 0.f, 0.f, 0.f};
            #pragma unroll
            for (int p = 0; p < 8; p++) {
                const char* pp = smx + 131072u + (unsigned)(p * 8192)
                               + (unsigned)r64 * 128u;
                float4 a = *(const float4*)(pp + c0);
                float4 b = *(const float4*)(pp + c1);
                s0.x += a.x; s0.y += a.y; s0.z += a.z; s0.w += a.w;
                s1.x += b.x; s1.y += b.y; s1.z += b.z; s1.w += b.w;
            }

            o0.x = fmaxf(x0p.x + s0.x, 0.f); o0.y = fmaxf(x0p.y + s0.y, 0.f);
            o0.z = fmaxf(x0p.z + s0.z, 0.f); o0.w = fmaxf(x0p.w + s0.w, 0.f);
            o1.x = fmaxf(x1p.x + s1.x, 0.f); o1.y = fmaxf(x1p.y + s1.y, 0.f);
            o1.z = fmaxf(x1p.z + s1.z, 0.f); o1.w = fmaxf(x1p.w + s1.w, 0.f);

            // write next-step permuted fragments FIRST (the only cross-CTA dep)
            float sv[8] = {o0.x, o0.y, o0.z, o0.w, o1.x, o1.y, o1.z, o1.w};
            unsigned* dh = (unsigned*)&g_Ap[t & 1][(tileE * 128 + gE) * 32];
            unsigned* dl = (unsigned*)&g_Ap[t & 1][(tileE * 128 + 64 + gE) * 32];
            #pragma unroll
            for (int j = 0; j < 4; j++) {
                float v0 = sv[2 * j], v1 = sv[2 * j + 1];
                __nv_bfloat16 h0 = __float2bfloat16(v0);
                __nv_bfloat16 h1 = __float2bfloat16(v1);
                unsigned hw = (unsigned)__bfloat16_as_ushort(h0)
                            | ((unsigned)__bfloat16_as_ushort(h1) << 16);
                __nv_bfloat16 l0 = __float2bfloat16(v0 - __bfloat162float(h0));
                __nv_bfloat16 l1 = __float2bfloat16(v1 - __bfloat162float(h1));
                unsigned lw = (unsigned)__bfloat16_as_ushort(l0)
                            | ((unsigned)__bfloat16_as_ushort(l1) << 16);
                const int L = ((rloc & 7) << 2) + j;
                dh[L * 4 + slot] = hw;
                dl[L * 4 + slot] = lw;
            }
        }

        if (t < TT - 1) {
            nbar++;
            // arrive early: fragments are published, then overlap the fp32
            // out-store with other CTAs' arrival.
            __syncthreads();
            if (tid == 0) {
                __threadfence();
                atomicAdd(barp, 1u);
            }
            *(float4*)po       = o0;
            *(float4*)(po + 4) = o1;
            if (tid == 0) {
                volatile unsigned* p = barp;
                const unsigned tgt = nbar * 32u;
                while (*p < tgt) __nanosleep(32);
                __threadfence();
            }
            __syncthreads();
        } else {
            *(float4*)po       = o0;
            *(float4*)(po + 4) = o1;
        }
    }
}

// ---------------------------------------------------------------------------
extern "C" void kernel_launch(void* const* d_in, const int* in_sizes, int n_in,
                              void* d_out, int out_size)
{
    const float* x   = (const float*)d_in[0];   // [256,512,512]
    const float* Wxh = (const float*)d_in[1];   // [512,1024]
    const float* bxh = (const float*)d_in[2];   // [1024]
    const float* Whh = (const float*)d_in[3];   // [1024,1024]
    float* out = (float*)d_out;                 // [256,512,1024]

    // Prep: weight splits
    wx_convert<<<(EE * HH) / 256, 256>>>(Wxh);
    wt_convert<<<(HH * HH) / 256, 256>>>(Whh);

    // Phase 1: xh -> d_out (tensor cores, bf16 hi/lo x3)
    const int smem_p1 = 2 * 32768;
    cudaFuncSetAttribute(gemm_xh_mma,
                         cudaFuncAttributeMaxDynamicSharedMemorySize, smem_p1);
    dim3 g1(HH / 128, (BB * TT) / 128);          // (8, 1024)
    gemm_xh_mma<<<g1, 256, smem_p1>>>(x, bxh, out);

    // h0 = relu(xh_0) + permuted fragment split
    init_h0<<<(BB * HH / 2) / 256, 256>>>(out);

    // Phase 2: persistent mma.sync scan (fragment-resident state)
    const int smem_p2 = 131072 + 65536;          // W 128KB + partials 64KB
    cudaFuncSetAttribute(rnn_scan_mma,
                         cudaFuncAttributeMaxDynamicSharedMemorySize, smem_p2);
    rnn_scan_mma<<<NCTA, 256, smem_p2>>>(out);

    // reset group barriers for next replay
    bar_reset<<<1, 128>>>();
}